// round 11
// baseline (speedup 1.0000x reference)
#include <cuda_runtime.h>
#include <cuda_bf16.h>
#include <math.h>
#include <stdint.h>

#define NMAX 100000
#define EMAX 1000000
#define KBLK 32
#define HTILE 32
#define SAS 40
#define SBS 42
#define HSAS 136
#define HSBS 136

// weight-plane offsets (bf16 elements, transposed [M][K])
#define OFF_WHULL 0
#define OFF_W1H   16384
#define OFF_W2H   32768
#define OFF_WCAT  65536
#define OFF_WUP   114688
#define OFF_WL0   147456
#define OFF_WL1   212992
#define WPLANE_TOTAL 278528

// ---------------- scratch ----------------
__device__ float    g_vhull[(size_t)NMAX * 128];
__device__ float    g_oh   [(size_t)NMAX * 128];
__device__ float    g_b256 [(size_t)NMAX * 256];
__device__ uint32_t g_vp   [(size_t)NMAX * 128];
__device__ uint32_t g_ohp  [(size_t)NMAX * 128];
__device__ uint32_t g_t128p[(size_t)NMAX * 128];
__device__ uint32_t g_a256p[(size_t)NMAX * 256];
__device__ uint32_t g_b256p[(size_t)NMAX * 256];
__device__ __nv_bfloat16 g_whi[WPLANE_TOTAL];
__device__ __nv_bfloat16 g_wlo[WPLANE_TOTAL];
// CSR scratch
__device__ int g_counts [NMAX];
__device__ int g_offsets[NMAX];
__device__ int g_running[NMAX];
__device__ int g_partial[128];
__device__ int g_eorder [EMAX];

__device__ __forceinline__ float silu_f(float x) { return x / (1.0f + expf(-x)); }

__device__ __forceinline__ uint32_t smem_u32(const void* p) {
    uint32_t a;
    asm("{ .reg .u64 t; cvta.to.shared.u64 t, %1; cvt.u32.u64 %0, t; }" : "=r"(a) : "l"(p));
    return a;
}

__device__ __forceinline__ void mma_bf16(float* c, uint32_t a0, uint32_t a1,
                                         uint32_t a2, uint32_t a3,
                                         uint32_t b0, uint32_t b1) {
    asm volatile(
        "mma.sync.aligned.m16n8k16.row.col.f32.bf16.bf16.f32 "
        "{%0,%1,%2,%3}, {%4,%5,%6,%7}, {%8,%9}, {%0,%1,%2,%3};"
        : "+f"(c[0]), "+f"(c[1]), "+f"(c[2]), "+f"(c[3])
        : "r"(a0), "r"(a1), "r"(a2), "r"(a3), "r"(b0), "r"(b1));
}

__device__ __forceinline__ void ldmx4(uint32_t& r0, uint32_t& r1,
                                      uint32_t& r2, uint32_t& r3, uint32_t addr) {
    asm volatile("ldmatrix.sync.aligned.m8n8.x4.shared.b16 {%0,%1,%2,%3}, [%4];"
                 : "=r"(r0), "=r"(r1), "=r"(r2), "=r"(r3) : "r"(addr));
}

__device__ __forceinline__ uint32_t pack_split(float f) {
    __nv_bfloat16 h = __float2bfloat16(f);
    __nv_bfloat16 l = __float2bfloat16(f - __bfloat162float(h));
    return (uint32_t)__bfloat16_as_ushort(h) | ((uint32_t)__bfloat16_as_ushort(l) << 16);
}

// ---------------- prep kernels ----------------
__global__ void pack_weight_kernel(const float* __restrict__ W,
                                   __nv_bfloat16* __restrict__ hiT,
                                   __nv_bfloat16* __restrict__ loT, int K, int M)
{
    int idx = blockIdx.x * blockDim.x + threadIdx.x;
    if (idx >= K * M) return;
    int k = idx / M, m = idx % M;
    float v = W[idx];
    __nv_bfloat16 h = __float2bfloat16(v);
    __nv_bfloat16 l = __float2bfloat16(v - __bfloat162float(h));
    hiT[(size_t)m * K + k] = h;
    loT[(size_t)m * K + k] = l;
}

__global__ void pack_act_kernel(const float* __restrict__ src,
                                uint32_t* __restrict__ dst, size_t n)
{
    size_t t = (size_t)blockIdx.x * blockDim.x + threadIdx.x;
    size_t stride = (size_t)gridDim.x * blockDim.x;
    for (size_t x = t; x < n; x += stride) dst[x] = pack_split(src[x]);
}

// ---------------- zero oh + counts ----------------
__global__ void zero_kernel(float* oh, int* counts, size_t n, int N)
{
    size_t t = (size_t)blockIdx.x * blockDim.x + threadIdx.x;
    size_t stride = (size_t)gridDim.x * blockDim.x;
    for (size_t x = t; x < n; x += stride) oh[x] = 0.0f;
    for (size_t x = t; x < (size_t)N; x += stride) counts[x] = 0;
}

// ---------------- CSR build ----------------
__global__ void hist_kernel(const int* __restrict__ idx, int* __restrict__ counts, int E)
{
    int e = blockIdx.x * blockDim.x + threadIdx.x;
    if (e < E) atomicAdd(&counts[idx[e]], 1);
}

__global__ void scanA_kernel(const int* __restrict__ counts,
                             int* __restrict__ offsets,
                             int* __restrict__ partial, int N)
{
    __shared__ int s[1024];
    int t = threadIdx.x;
    int i = blockIdx.x * 1024 + t;
    int v = (i < N) ? counts[i] : 0;
    s[t] = v;
    __syncthreads();
#pragma unroll
    for (int o = 1; o < 1024; o <<= 1) {
        int x = (t >= o) ? s[t - o] : 0;
        __syncthreads();
        s[t] += x;
        __syncthreads();
    }
    if (i < N) offsets[i] = s[t] - v;
    if (t == 1023) partial[blockIdx.x] = s[1023];
}

__global__ void scanB_kernel(int* __restrict__ partial, int nb)
{
    if (threadIdx.x == 0 && blockIdx.x == 0) {
        int run = 0;
        for (int i = 0; i < nb; i++) { int t = partial[i]; partial[i] = run; run += t; }
    }
}

__global__ void scanC_kernel(int* __restrict__ offsets,
                             const int* __restrict__ partial,
                             int* __restrict__ running, int N)
{
    int i = blockIdx.x * blockDim.x + threadIdx.x;
    if (i < N) {
        int o = offsets[i] + partial[i >> 10];
        offsets[i] = o;
        running[i] = o;
    }
}

__global__ void fill_kernel(const int* __restrict__ idx,
                            int* __restrict__ running,
                            int* __restrict__ eorder, int E)
{
    int e = blockIdx.x * blockDim.x + threadIdx.x;
    if (e < E) {
        int slot = atomicAdd(&running[idx[e]], 1);
        eorder[slot] = e;
    }
}

// warp per node: sequential sum of its edges' rows; writes packed v directly
__global__ void csr_sum_kernel(const float4* __restrict__ e2,
                               const int* __restrict__ eorder,
                               const int* __restrict__ offsets,
                               const int* __restrict__ counts,
                               uint32_t* __restrict__ vp, int N)
{
    int gwarp = (blockIdx.x * blockDim.x + threadIdx.x) >> 5;
    int lane = threadIdx.x & 31;
    if (gwarp >= N) return;
    int beg = offsets[gwarp];
    int end = beg + counts[gwarp];
    float4 acc = make_float4(0.f, 0.f, 0.f, 0.f);
    for (int k = beg; k < end; k++) {
        int row = eorder[k];
        float4 v = e2[(size_t)row * 32 + lane];
        acc.x += v.x; acc.y += v.y; acc.z += v.z; acc.w += v.w;
    }
    uint4 o;
    o.x = pack_split(acc.x); o.y = pack_split(acc.y);
    o.z = pack_split(acc.z); o.w = pack_split(acc.w);
    *(uint4*)&vp[(size_t)gwarp * 128 + lane * 4] = o;
}

__global__ void out_kernel(const float* __restrict__ A,
                           const float* __restrict__ w,
                           float* __restrict__ out, int Nrows)
{
    int gwarp = (blockIdx.x * blockDim.x + threadIdx.x) >> 5;
    int lane = threadIdx.x & 31;
    if (gwarp >= Nrows) return;
    const float* row = A + (size_t)gwarp * 256;
    float acc = 0.0f;
#pragma unroll
    for (int k = lane; k < 256; k += 32) acc += row[k] * __ldg(&w[k]);
#pragma unroll
    for (int o = 16; o > 0; o >>= 1) acc += __shfl_down_sync(0xffffffff, acc, o);
    if (lane == 0) out[gwarp] = acc;
}

// ---------------- warp-MMA bf16 split-3 GEMM: 64x64 warp tiles ----------------
// CTA 128x128, 4 warps (2 row x 2 col), 128 threads.
// Per warp-kchunk: 64 LDS : 96 HMMA (0.67:1, was 1:1).
__global__ __launch_bounds__(128, 2) void gemm_mma(
    const uint32_t* __restrict__ A0, int lda0, int ksplit,
    const uint32_t* __restrict__ A1, int lda1,
    const __nv_bfloat16* __restrict__ WhiT, const __nv_bfloat16* __restrict__ WloT,
    int ldw, const float* __restrict__ bias,
    void* __restrict__ Cout, int outPacked,
    int Nrows, int K, int M, int act)
{
    __shared__ __nv_bfloat16 sAhi[128 * SAS];
    __shared__ __nv_bfloat16 sAlo[128 * SAS];
    __shared__ __nv_bfloat16 sBhi[128 * SBS];
    __shared__ __nv_bfloat16 sBlo[128 * SBS];

    int tid = threadIdx.x;
    int wid = tid >> 5;
    int lane = tid & 31;
    int warpRow = wid & 1;       // 2 x 64 rows
    int warpCol = wid >> 1;      // 2 x 64 cols
    int row0 = blockIdx.x * 128;
    int col0 = blockIdx.y * 128;

    float c[4][8][4];
#pragma unroll
    for (int mf = 0; mf < 4; mf++)
#pragma unroll
        for (int nf = 0; nf < 8; nf++)
#pragma unroll
            for (int q = 0; q < 4; q++) c[mf][nf][q] = 0.0f;

    int qrow = lane >> 2;
    int qcol = lane & 3;

    for (int k0 = 0; k0 < K; k0 += KBLK) {
        const uint32_t* srcA;
        int kbase, ld;
        if (k0 < ksplit) { srcA = A0; kbase = k0; ld = lda0; }
        else             { srcA = A1; kbase = k0 - ksplit; ld = lda1; }
        // ---- A tile: 128x32 packed -> hi/lo (1024 uint4, 128 threads) ----
#pragma unroll
        for (int it = 0; it < 8; it++) {
            int idx = tid + it * 128;
            int r = idx >> 3;
            int kq = (idx & 7) * 4;
            uint4 u = make_uint4(0u, 0u, 0u, 0u);
            int grow = row0 + r;
            if (grow < Nrows)
                u = *(const uint4*)&srcA[(size_t)grow * ld + kbase + kq];
            uint32_t hi01 = __byte_perm(u.x, u.y, 0x5410);
            uint32_t lo01 = __byte_perm(u.x, u.y, 0x7632);
            uint32_t hi23 = __byte_perm(u.z, u.w, 0x5410);
            uint32_t lo23 = __byte_perm(u.z, u.w, 0x7632);
            int base = r * SAS + kq;
            *(uint2*)&sAhi[base] = make_uint2(hi01, hi23);
            *(uint2*)&sAlo[base] = make_uint2(lo01, lo23);
        }
        // ---- B tile: copy from transposed pre-split planes ----
#pragma unroll
        for (int it = 0; it < 8; it++) {
            int idx = tid + it * 128;
            int n = idx >> 3;
            int kq = (idx & 7) * 4;
            size_t goff = (size_t)(col0 + n) * ldw + k0 + kq;
            uint2 uh = *(const uint2*)&WhiT[goff];
            uint2 ul = *(const uint2*)&WloT[goff];
            int b = n * SBS + kq;
            *(uint32_t*)&sBhi[b]     = uh.x;
            *(uint32_t*)&sBhi[b + 2] = uh.y;
            *(uint32_t*)&sBlo[b]     = ul.x;
            *(uint32_t*)&sBlo[b + 2] = ul.y;
        }
        __syncthreads();

#pragma unroll
        for (int kc = 0; kc < KBLK; kc += 16) {
            uint32_t ah[4][4], al[4][4];
#pragma unroll
            for (int mf = 0; mf < 4; mf++) {
                int r = warpRow * 64 + mf * 16 + qrow;
                int i0 = r * SAS + kc + 2 * qcol;
                ah[mf][0] = *(const uint32_t*)&sAhi[i0];
                ah[mf][1] = *(const uint32_t*)&sAhi[i0 + 8 * SAS];
                ah[mf][2] = *(const uint32_t*)&sAhi[i0 + 8];
                ah[mf][3] = *(const uint32_t*)&sAhi[i0 + 8 * SAS + 8];
                al[mf][0] = *(const uint32_t*)&sAlo[i0];
                al[mf][1] = *(const uint32_t*)&sAlo[i0 + 8 * SAS];
                al[mf][2] = *(const uint32_t*)&sAlo[i0 + 8];
                al[mf][3] = *(const uint32_t*)&sAlo[i0 + 8 * SAS + 8];
            }
#pragma unroll
            for (int nf = 0; nf < 8; nf++) {
                int n = warpCol * 64 + nf * 8 + qrow;
                int i0 = n * SBS + kc + 2 * qcol;
                uint32_t bh0 = *(const uint32_t*)&sBhi[i0];
                uint32_t bh1 = *(const uint32_t*)&sBhi[i0 + 8];
                uint32_t bl0 = *(const uint32_t*)&sBlo[i0];
                uint32_t bl1 = *(const uint32_t*)&sBlo[i0 + 8];
#pragma unroll
                for (int mf = 0; mf < 4; mf++) {
                    mma_bf16(c[mf][nf], ah[mf][0], ah[mf][1], ah[mf][2], ah[mf][3], bh0, bh1);
                    mma_bf16(c[mf][nf], ah[mf][0], ah[mf][1], ah[mf][2], ah[mf][3], bl0, bl1);
                    mma_bf16(c[mf][nf], al[mf][0], al[mf][1], al[mf][2], al[mf][3], bh0, bh1);
                }
            }
        }
        __syncthreads();
    }

    // ---- epilogue ----
#pragma unroll
    for (int mf = 0; mf < 4; mf++) {
        int rbase = row0 + warpRow * 64 + mf * 16 + qrow;
#pragma unroll
        for (int nf = 0; nf < 8; nf++) {
            int colp = col0 + warpCol * 64 + nf * 8 + 2 * qcol;
            float b0v = 0.f, b1v = 0.f;
            if (bias) { b0v = bias[colp]; b1v = bias[colp + 1]; }
            float f0 = c[mf][nf][0] + b0v;
            float f1 = c[mf][nf][1] + b1v;
            float f2 = c[mf][nf][2] + b0v;
            float f3 = c[mf][nf][3] + b1v;
            if (act) { f0 = silu_f(f0); f1 = silu_f(f1); f2 = silu_f(f2); f3 = silu_f(f3); }
            if (outPacked) {
                uint32_t* Cp = (uint32_t*)Cout;
                if (rbase < Nrows)
                    *(uint2*)&Cp[(size_t)rbase * M + colp] =
                        make_uint2(pack_split(f0), pack_split(f1));
                if (rbase + 8 < Nrows)
                    *(uint2*)&Cp[(size_t)(rbase + 8) * M + colp] =
                        make_uint2(pack_split(f2), pack_split(f3));
            } else {
                float* Cf = (float*)Cout;
                if (rbase < Nrows)
                    *(float2*)&Cf[(size_t)rbase * M + colp] = make_float2(f0, f1);
                if (rbase + 8 < Nrows)
                    *(float2*)&Cf[(size_t)(rbase + 8) * M + colp] = make_float2(f2, f3);
            }
        }
    }
}

// ---------------- hull kernel (unchanged, measured 331 us) ----------
#define HULL_SMEM_BYTES ((2 * 128 * HSBS + 2 * HTILE * HSAS) * 2 + (HTILE * 16 + 128) * 4)

__global__ __launch_bounds__(256, 2) void hull_kernel(
    const float* __restrict__ fea,
    const int* __restrict__ jidx, const int* __restrict__ iidx,
    const float* __restrict__ w0, const float* __restrict__ b0,
    const float* __restrict__ w1, const float* __restrict__ b1,
    const float* __restrict__ vhull, float* __restrict__ oh, int EHn)
{
    extern __shared__ char smraw[];
    __nv_bfloat16* s_w1hi  = (__nv_bfloat16*)smraw;
    __nv_bfloat16* s_w1lo  = s_w1hi + 128 * HSBS;
    __nv_bfloat16* s_hidhi = s_w1lo + 128 * HSBS;
    __nv_bfloat16* s_hidlo = s_hidhi + HTILE * HSAS;
    float* s_fea = (float*)(s_hidlo + HTILE * HSAS);
    float* s_b1  = s_fea + HTILE * 16;

    int tid = threadIdx.x;
    int wid = tid >> 5;
    int lane = tid & 31;
    int warpRow = wid & 1;
    int warpCol = wid >> 1;
    int qrow = lane >> 2;
    int qcol = lane & 3;
    int col = tid & 127;
    int wg  = tid >> 7;
    int g  = lane >> 3;
    int lr = lane & 7;

    for (int t = tid; t < 16384; t += 256) {
        int k = t >> 7, n = t & 127;
        float v = w1[t];
        __nv_bfloat16 h = __float2bfloat16(v);
        __nv_bfloat16 l = __float2bfloat16(v - __bfloat162float(h));
        s_w1hi[n * HSBS + k] = h;
        s_w1lo[n * HSBS + k] = l;
    }
    if (tid < 128) s_b1[tid] = b1[tid];
    float rw0[16];
#pragma unroll
    for (int k = 0; k < 16; k++) rw0[k] = w0[k * 128 + col];
    float rb0 = b0[col];

    uint32_t bHhi = smem_u32(s_hidhi), bHlo = smem_u32(s_hidlo);
    uint32_t bWhi = smem_u32(s_w1hi),  bWlo = smem_u32(s_w1lo);
    uint32_t aRowPart = (uint32_t)((warpRow * 16 + (g & 1) * 8 + lr) * HSAS * 2
                                   + (g >> 1) * 16);
    uint32_t bRowPart[2];
#pragma unroll
    for (int p = 0; p < 2; p++)
        bRowPart[p] = (uint32_t)(((warpCol * 32 + (2 * p + (g >> 1)) * 8 + lr) * HSBS
                                  + (g & 1) * 8) * 2);
    __syncthreads();

    for (int base = blockIdx.x * HTILE; base < EHn; base += gridDim.x * HTILE) {
        int ec = min(HTILE, EHn - base);

        for (int t = tid; t < ec * 16; t += 256)
            s_fea[t] = fea[(size_t)base * 16 + t];
        __syncthreads();

        int e0 = wg * 16, e1 = min(ec, e0 + 16);
        for (int e = e0; e < e1; e++) {
            float acc = rb0;
#pragma unroll
            for (int k = 0; k < 16; k++)
                acc += s_fea[e * 16 + k] * rw0[k];
            float hv = silu_f(acc);
            __nv_bfloat16 h = __float2bfloat16(hv);
            __nv_bfloat16 l = __float2bfloat16(hv - __bfloat162float(h));
            s_hidhi[e * HSAS + col] = h;
            s_hidlo[e * HSAS + col] = l;
        }
        __syncthreads();

        float c[4][4];
#pragma unroll
        for (int nf = 0; nf < 4; nf++)
#pragma unroll
            for (int q = 0; q < 4; q++) c[nf][q] = 0.0f;

#pragma unroll
        for (int kc = 0; kc < 128; kc += 16) {
            uint32_t kOff = kc * 2;
            uint32_t ah0, ah1, ah2, ah3, al0, al1, al2, al3;
            ldmx4(ah0, ah1, ah2, ah3, bHhi + aRowPart + kOff);
            ldmx4(al0, al1, al2, al3, bHlo + aRowPart + kOff);
#pragma unroll
            for (int p = 0; p < 2; p++) {
                uint32_t bh0, bh1, bh2, bh3, bl0, bl1, bl2, bl3;
                ldmx4(bh0, bh1, bh2, bh3, bWhi + bRowPart[p] + kOff);
                ldmx4(bl0, bl1, bl2, bl3, bWlo + bRowPart[p] + kOff);
                mma_bf16(c[2*p],   ah0, ah1, ah2, ah3, bh0, bh1);
                mma_bf16(c[2*p],   ah0, ah1, ah2, ah3, bl0, bl1);
                mma_bf16(c[2*p],   al0, al1, al2, al3, bh0, bh1);
                mma_bf16(c[2*p+1], ah0, ah1, ah2, ah3, bh2, bh3);
                mma_bf16(c[2*p+1], ah0, ah1, ah2, ah3, bl2, bl3);
                mma_bf16(c[2*p+1], al0, al1, al2, al3, bh2, bh3);
            }
        }

        int eA = warpRow * 16 + qrow;
        int eB = eA + 8;
        int jA = 0, iA = 0, jB = 0, iB = 0;
        bool vA = eA < ec, vB = eB < ec;
        if (vA) { jA = jidx[base + eA]; iA = iidx[base + eA]; }
        if (vB) { jB = jidx[base + eB]; iB = iidx[base + eB]; }
#pragma unroll
        for (int nf = 0; nf < 4; nf++) {
            int cp = warpCol * 32 + nf * 8 + 2 * qcol;
            float bb0 = s_b1[cp], bb1 = s_b1[cp + 1];
            if (vA) {
                float2 vh = *(const float2*)&vhull[(size_t)jA * 128 + cp];
                float f0 = (c[nf][0] + bb0) * vh.x;
                float f1 = (c[nf][1] + bb1) * vh.y;
                atomicAdd(&oh[(size_t)iA * 128 + cp], f0);
                atomicAdd(&oh[(size_t)iA * 128 + cp + 1], f1);
            }
            if (vB) {
                float2 vh = *(const float2*)&vhull[(size_t)jB * 128 + cp];
                float f2 = (c[nf][2] + bb0) * vh.x;
                float f3 = (c[nf][3] + bb1) * vh.y;
                atomicAdd(&oh[(size_t)iB * 128 + cp], f2);
                atomicAdd(&oh[(size_t)iB * 128 + cp + 1], f3);
            }
        }
        __syncthreads();
    }
}

// ---------------- launch ----------------
static void launch_gemm(const uint32_t* A0, int lda0, int ksplit,
                        const uint32_t* A1, int lda1,
                        const __nv_bfloat16* whiT, const __nv_bfloat16* wloT, int ldw,
                        const float* bias, void* C, int outPacked,
                        int N, int K, int M, int act)
{
    dim3 grid((N + 127) / 128, M / 128);
    gemm_mma<<<grid, 128>>>(A0, lda0, ksplit, A1, lda1, whiT, wloT, ldw,
                            bias, C, outPacked, N, K, M, act);
}

extern "C" void kernel_launch(void* const* d_in, const int* in_sizes, int n_in,
                              void* d_out, int out_size)
{
    const float* e2    = (const float*)d_in[0];
    const int*   iedge = (const int*)  d_in[1];
    const float* fea   = (const float*)d_in[2];
    const int*   eih   = (const int*)  d_in[3];
    const float* w_hull= (const float*)d_in[4];
    const float* w0    = (const float*)d_in[5];
    const float* b0    = (const float*)d_in[6];
    const float* w1    = (const float*)d_in[7];
    const float* b1    = (const float*)d_in[8];
    const float* w1h   = (const float*)d_in[9];
    const float* b1h   = (const float*)d_in[10];
    const float* w2h   = (const float*)d_in[11];
    const float* b2h   = (const float*)d_in[12];
    const float* wcat  = (const float*)d_in[13];
    const float* bcat  = (const float*)d_in[14];
    const float* wup   = (const float*)d_in[15];
    const float* bup   = (const float*)d_in[16];
    const float* wl0   = (const float*)d_in[17];
    const float* bl0   = (const float*)d_in[18];
    const float* wl1   = (const float*)d_in[19];
    const float* bl1   = (const float*)d_in[20];
    const float* wout  = (const float*)d_in[21];
    float* out = (float*)d_out;

    int N  = out_size;
    int E  = in_sizes[1];
    int EH = in_sizes[2] / 16;
    const int* jh = eih;
    const int* ih = eih + EH;

    float *pvh, *poh, *pb;
    uint32_t *pvp, *pohp, *pt128p, *pa256p, *pb256p;
    __nv_bfloat16 *pwhi, *pwlo;
    int *pcnt, *poff, *prun, *ppart, *peord;
    cudaGetSymbolAddress((void**)&pvh,    g_vhull);
    cudaGetSymbolAddress((void**)&poh,    g_oh);
    cudaGetSymbolAddress((void**)&pb,     g_b256);
    cudaGetSymbolAddress((void**)&pvp,    g_vp);
    cudaGetSymbolAddress((void**)&pohp,   g_ohp);
    cudaGetSymbolAddress((void**)&pt128p, g_t128p);
    cudaGetSymbolAddress((void**)&pa256p, g_a256p);
    cudaGetSymbolAddress((void**)&pb256p, g_b256p);
    cudaGetSymbolAddress((void**)&pwhi,   g_whi);
    cudaGetSymbolAddress((void**)&pwlo,   g_wlo);
    cudaGetSymbolAddress((void**)&pcnt,   g_counts);
    cudaGetSymbolAddress((void**)&poff,   g_offsets);
    cudaGetSymbolAddress((void**)&prun,   g_running);
    cudaGetSymbolAddress((void**)&ppart,  g_partial);
    cudaGetSymbolAddress((void**)&peord,  g_eorder);

    cudaFuncSetAttribute(hull_kernel, cudaFuncAttributeMaxDynamicSharedMemorySize,
                         HULL_SMEM_BYTES);
    cudaFuncSetAttribute(hull_kernel, cudaFuncAttributePreferredSharedMemoryCarveout,
                         100);

    // 0. pre-split weights into transposed bf16 planes
    {
        struct { const float* w; int off, K, M; } ws[7] = {
            { w_hull, OFF_WHULL, 128, 128 },
            { w1h,    OFF_W1H,   128, 128 },
            { w2h,    OFF_W2H,   128, 256 },
            { wcat,   OFF_WCAT,  384, 128 },
            { wup,    OFF_WUP,   128, 256 },
            { wl0,    OFF_WL0,   256, 256 },
            { wl1,    OFF_WL1,   256, 256 },
        };
        for (int i = 0; i < 7; i++) {
            int n = ws[i].K * ws[i].M;
            pack_weight_kernel<<<(n + 255) / 256, 256>>>(
                ws[i].w, pwhi + ws[i].off, pwlo + ws[i].off, ws[i].K, ws[i].M);
        }
    }

    // 1. zero oh + counts
    zero_kernel<<<2048, 256>>>(poh, pcnt, (size_t)N * 128, N);

    // 2. CSR build + segment-sum -> packed v
    int nb = (N + 1023) / 1024;
    hist_kernel<<<(E + 255) / 256, 256>>>(iedge, pcnt, E);
    scanA_kernel<<<nb, 1024>>>(pcnt, poff, ppart, N);
    scanB_kernel<<<1, 32>>>(ppart, nb);
    scanC_kernel<<<(N + 255) / 256, 256>>>(poff, ppart, prun, N);
    fill_kernel<<<(E + 255) / 256, 256>>>(iedge, prun, peord, E);
    csr_sum_kernel<<<(N * 32 + 255) / 256, 256>>>(
        (const float4*)e2, peord, poff, pcnt, pvp, N);

    // 3. v_hull = v @ w_hull (fp32 out for hull gather)
    launch_gemm(pvp, 128, 128, pvp, 128, pwhi + OFF_WHULL, pwlo + OFF_WHULL, 128,
                nullptr, pvh, 0, N, 128, 128, 0);

    // 4. hull message passing; pack oh
    hull_kernel<<<296, 256, HULL_SMEM_BYTES>>>(
        fea, jh, ih, w0, b0, w1, b1, pvh, poh, EH);
    pack_act_kernel<<<2048, 256>>>(poh, pohp, (size_t)N * 128);

    // 5. t128p = silu(oh @ w1_hull + b1_hull)
    launch_gemm(pohp, 128, 128, pohp, 128, pwhi + OFF_W1H, pwlo + OFF_W1H, 128,
                b1h, pt128p, 1, N, 128, 128, 1);
    // 6. a256p = t128 @ w2_hull + b2_hull
    launch_gemm(pt128p, 128, 128, pt128p, 128, pwhi + OFF_W2H, pwlo + OFF_W2H, 128,
                b2h, pa256p, 1, N, 128, 256, 0);
    // 7. t128p = silu([v | a256] @ w_cat + b_cat)   (K = 384)
    launch_gemm(pvp, 128, 128, pa256p, 256, pwhi + OFF_WCAT, pwlo + OFF_WCAT, 384,
                bcat, pt128p, 1, N, 384, 128, 1);
    // 8. b256p = t128 @ w_up + b_up
    launch_gemm(pt128p, 128, 128, pt128p, 128, pwhi + OFF_WUP, pwlo + OFF_WUP, 128,
                bup, pb256p, 1, N, 128, 256, 0);
    // 9. a256p = silu(b256 @ w_l0 + b_l0)
    launch_gemm(pb256p, 256, 256, pb256p, 256, pwhi + OFF_WL0, pwlo + OFF_WL0, 256,
                bl0, pa256p, 1, N, 256, 256, 1);
    // 10. b256 (fp32) = silu(a256 @ w_l1 + b_l1)
    launch_gemm(pa256p, 256, 256, pa256p, 256, pwhi + OFF_WL1, pwlo + OFF_WL1, 256,
                bl1, pb, 0, N, 256, 256, 1);
    // 11. out = b256 @ w_out
    {
        int blocks = (N + 7) / 8;
        out_kernel<<<blocks, 256>>>(pb, wout, out, N);
    }
}

// round 13
// speedup vs baseline: 1.1349x; 1.1349x over previous
#include <cuda_runtime.h>
#include <cuda_bf16.h>
#include <math.h>
#include <stdint.h>

#define NMAX 100000
#define EMAX 1000000
#define KBLK 32
#define HTILE 32
#define SAS 40
#define SBS 42
#define HSAS 136
#define HSBS 136

// weight-plane offsets (bf16 elements, transposed [M][K])
#define OFF_WHULL 0
#define OFF_W1H   16384
#define OFF_W2H   32768
#define OFF_WCAT  65536
#define OFF_WUP   114688
#define OFF_WL0   147456
#define OFF_WL1   212992
#define WPLANE_TOTAL 278528

// ---------------- scratch ----------------
__device__ float    g_vhull[(size_t)NMAX * 128];
__device__ float    g_oh   [(size_t)NMAX * 128];
__device__ uint32_t g_vp   [(size_t)NMAX * 128];
__device__ uint32_t g_ohp  [(size_t)NMAX * 128];
__device__ uint32_t g_t128p[(size_t)NMAX * 128];
__device__ uint32_t g_a256p[(size_t)NMAX * 256];
__device__ uint32_t g_b256p[(size_t)NMAX * 256];
__device__ __nv_bfloat16 g_whi[WPLANE_TOTAL];
__device__ __nv_bfloat16 g_wlo[WPLANE_TOTAL];
// CSR scratch
__device__ int g_counts [NMAX];
__device__ int g_offsets[NMAX];
__device__ int g_running[NMAX];
__device__ int g_partial[128];
__device__ int g_eorder [EMAX];

__device__ __forceinline__ float silu_f(float x) { return x / (1.0f + expf(-x)); }

__device__ __forceinline__ uint32_t smem_u32(const void* p) {
    uint32_t a;
    asm("{ .reg .u64 t; cvta.to.shared.u64 t, %1; cvt.u32.u64 %0, t; }" : "=r"(a) : "l"(p));
    return a;
}

__device__ __forceinline__ void mma_bf16(float* c, uint32_t a0, uint32_t a1,
                                         uint32_t a2, uint32_t a3,
                                         uint32_t b0, uint32_t b1) {
    asm volatile(
        "mma.sync.aligned.m16n8k16.row.col.f32.bf16.bf16.f32 "
        "{%0,%1,%2,%3}, {%4,%5,%6,%7}, {%8,%9}, {%0,%1,%2,%3};"
        : "+f"(c[0]), "+f"(c[1]), "+f"(c[2]), "+f"(c[3])
        : "r"(a0), "r"(a1), "r"(a2), "r"(a3), "r"(b0), "r"(b1));
}

__device__ __forceinline__ void ldmx4(uint32_t& r0, uint32_t& r1,
                                      uint32_t& r2, uint32_t& r3, uint32_t addr) {
    asm volatile("ldmatrix.sync.aligned.m8n8.x4.shared.b16 {%0,%1,%2,%3}, [%4];"
                 : "=r"(r0), "=r"(r1), "=r"(r2), "=r"(r3) : "r"(addr));
}

__device__ __forceinline__ uint32_t pack_split(float f) {
    __nv_bfloat16 h = __float2bfloat16(f);
    __nv_bfloat16 l = __float2bfloat16(f - __bfloat162float(h));
    return (uint32_t)__bfloat16_as_ushort(h) | ((uint32_t)__bfloat16_as_ushort(l) << 16);
}

// ---------------- prep kernels ----------------
__global__ void pack_weight_kernel(const float* __restrict__ W,
                                   __nv_bfloat16* __restrict__ hiT,
                                   __nv_bfloat16* __restrict__ loT, int K, int M)
{
    int idx = blockIdx.x * blockDim.x + threadIdx.x;
    if (idx >= K * M) return;
    int k = idx / M, m = idx % M;
    float v = W[idx];
    __nv_bfloat16 h = __float2bfloat16(v);
    __nv_bfloat16 l = __float2bfloat16(v - __bfloat162float(h));
    hiT[(size_t)m * K + k] = h;
    loT[(size_t)m * K + k] = l;
}

__global__ void pack_act_kernel(const float* __restrict__ src,
                                uint32_t* __restrict__ dst, size_t n)
{
    size_t t = (size_t)blockIdx.x * blockDim.x + threadIdx.x;
    size_t stride = (size_t)gridDim.x * blockDim.x;
    for (size_t x = t; x < n; x += stride) dst[x] = pack_split(src[x]);
}

// ---------------- zero oh + counts + out ----------------
__global__ void zero_kernel(float* oh, int* counts, float* outv, size_t n, int N)
{
    size_t t = (size_t)blockIdx.x * blockDim.x + threadIdx.x;
    size_t stride = (size_t)gridDim.x * blockDim.x;
    for (size_t x = t; x < n; x += stride) oh[x] = 0.0f;
    for (size_t x = t; x < (size_t)N; x += stride) { counts[x] = 0; outv[x] = 0.0f; }
}

// ---------------- CSR build ----------------
__global__ void hist_kernel(const int* __restrict__ idx, int* __restrict__ counts, int E)
{
    int e = blockIdx.x * blockDim.x + threadIdx.x;
    if (e < E) atomicAdd(&counts[idx[e]], 1);
}

__global__ void scanA_kernel(const int* __restrict__ counts,
                             int* __restrict__ offsets,
                             int* __restrict__ partial, int N)
{
    __shared__ int s[1024];
    int t = threadIdx.x;
    int i = blockIdx.x * 1024 + t;
    int v = (i < N) ? counts[i] : 0;
    s[t] = v;
    __syncthreads();
#pragma unroll
    for (int o = 1; o < 1024; o <<= 1) {
        int x = (t >= o) ? s[t - o] : 0;
        __syncthreads();
        s[t] += x;
        __syncthreads();
    }
    if (i < N) offsets[i] = s[t] - v;
    if (t == 1023) partial[blockIdx.x] = s[1023];
}

__global__ void scanB_kernel(int* __restrict__ partial, int nb)
{
    if (threadIdx.x == 0 && blockIdx.x == 0) {
        int run = 0;
        for (int i = 0; i < nb; i++) { int t = partial[i]; partial[i] = run; run += t; }
    }
}

__global__ void scanC_kernel(int* __restrict__ offsets,
                             const int* __restrict__ partial,
                             int* __restrict__ running, int N)
{
    int i = blockIdx.x * blockDim.x + threadIdx.x;
    if (i < N) {
        int o = offsets[i] + partial[i >> 10];
        offsets[i] = o;
        running[i] = o;
    }
}

__global__ void fill_kernel(const int* __restrict__ idx,
                            int* __restrict__ running,
                            int* __restrict__ eorder, int E)
{
    int e = blockIdx.x * blockDim.x + threadIdx.x;
    if (e < E) {
        int slot = atomicAdd(&running[idx[e]], 1);
        eorder[slot] = e;
    }
}

// warp per node: sequential sum of its edges' rows; writes packed v directly
__global__ void csr_sum_kernel(const float4* __restrict__ e2,
                               const int* __restrict__ eorder,
                               const int* __restrict__ offsets,
                               const int* __restrict__ counts,
                               uint32_t* __restrict__ vp, int N)
{
    int gwarp = (blockIdx.x * blockDim.x + threadIdx.x) >> 5;
    int lane = threadIdx.x & 31;
    if (gwarp >= N) return;
    int beg = offsets[gwarp];
    int end = beg + counts[gwarp];
    float4 acc = make_float4(0.f, 0.f, 0.f, 0.f);
    for (int k = beg; k < end; k++) {
        int row = eorder[k];
        float4 v = e2[(size_t)row * 32 + lane];
        acc.x += v.x; acc.y += v.y; acc.z += v.z; acc.w += v.w;
    }
    uint4 o;
    o.x = pack_split(acc.x); o.y = pack_split(acc.y);
    o.z = pack_split(acc.z); o.w = pack_split(acc.w);
    *(uint4*)&vp[(size_t)gwarp * 128 + lane * 4] = o;
}

// ---------------- warp-MMA bf16 split-3 GEMM (R10 proven core) ----------------
// Optional fused final projection: if wout != nullptr, after act the tile is
// dotted with wout[col] and atomically accumulated into outv[row] (no C store).
__global__ __launch_bounds__(256, 2) void gemm_mma(
    const uint32_t* __restrict__ A0, int lda0, int ksplit,
    const uint32_t* __restrict__ A1, int lda1,
    const __nv_bfloat16* __restrict__ WhiT, const __nv_bfloat16* __restrict__ WloT,
    int ldw, const float* __restrict__ bias,
    void* __restrict__ Cout, int outPacked,
    const float* __restrict__ wout, float* __restrict__ outv,
    int Nrows, int K, int M, int act)
{
    __shared__ __nv_bfloat16 sAhi[128 * SAS];
    __shared__ __nv_bfloat16 sAlo[128 * SAS];
    __shared__ __nv_bfloat16 sBhi[128 * SBS];
    __shared__ __nv_bfloat16 sBlo[128 * SBS];

    int tid = threadIdx.x;
    int wid = tid >> 5;
    int lane = tid & 31;
    int warpRow = wid & 3;
    int warpCol = wid >> 2;
    int row0 = blockIdx.x * 128;
    int col0 = blockIdx.y * 128;

    float c[2][8][4];
#pragma unroll
    for (int mf = 0; mf < 2; mf++)
#pragma unroll
        for (int nf = 0; nf < 8; nf++)
#pragma unroll
            for (int q = 0; q < 4; q++) c[mf][nf][q] = 0.0f;

    int qrow = lane >> 2;
    int qcol = lane & 3;

    for (int k0 = 0; k0 < K; k0 += KBLK) {
        const uint32_t* srcA;
        int kbase, ld;
        if (k0 < ksplit) { srcA = A0; kbase = k0; ld = lda0; }
        else             { srcA = A1; kbase = k0 - ksplit; ld = lda1; }
#pragma unroll
        for (int it = 0; it < 4; it++) {
            int idx = tid + it * 256;
            int r = idx >> 3;
            int kq = (idx & 7) * 4;
            uint4 u = make_uint4(0u, 0u, 0u, 0u);
            int grow = row0 + r;
            if (grow < Nrows)
                u = *(const uint4*)&srcA[(size_t)grow * ld + kbase + kq];
            uint32_t hi01 = __byte_perm(u.x, u.y, 0x5410);
            uint32_t lo01 = __byte_perm(u.x, u.y, 0x7632);
            uint32_t hi23 = __byte_perm(u.z, u.w, 0x5410);
            uint32_t lo23 = __byte_perm(u.z, u.w, 0x7632);
            int base = r * SAS + kq;
            *(uint2*)&sAhi[base] = make_uint2(hi01, hi23);
            *(uint2*)&sAlo[base] = make_uint2(lo01, lo23);
        }
#pragma unroll
        for (int it = 0; it < 4; it++) {
            int idx = tid + it * 256;
            int n = idx >> 3;
            int kq = (idx & 7) * 4;
            size_t goff = (size_t)(col0 + n) * ldw + k0 + kq;
            uint2 uh = *(const uint2*)&WhiT[goff];
            uint2 ul = *(const uint2*)&WloT[goff];
            int b = n * SBS + kq;
            *(uint32_t*)&sBhi[b]     = uh.x;
            *(uint32_t*)&sBhi[b + 2] = uh.y;
            *(uint32_t*)&sBlo[b]     = ul.x;
            *(uint32_t*)&sBlo[b + 2] = ul.y;
        }
        __syncthreads();

#pragma unroll
        for (int kc = 0; kc < KBLK; kc += 16) {
            uint32_t ah[2][4], al[2][4];
#pragma unroll
            for (int mf = 0; mf < 2; mf++) {
                int r = warpRow * 32 + mf * 16 + qrow;
                int i0 = r * SAS + kc + 2 * qcol;
                ah[mf][0] = *(const uint32_t*)&sAhi[i0];
                ah[mf][1] = *(const uint32_t*)&sAhi[i0 + 8 * SAS];
                ah[mf][2] = *(const uint32_t*)&sAhi[i0 + 8];
                ah[mf][3] = *(const uint32_t*)&sAhi[i0 + 8 * SAS + 8];
                al[mf][0] = *(const uint32_t*)&sAlo[i0];
                al[mf][1] = *(const uint32_t*)&sAlo[i0 + 8 * SAS];
                al[mf][2] = *(const uint32_t*)&sAlo[i0 + 8];
                al[mf][3] = *(const uint32_t*)&sAlo[i0 + 8 * SAS + 8];
            }
#pragma unroll
            for (int nf = 0; nf < 8; nf++) {
                int n = warpCol * 64 + nf * 8 + qrow;
                int i0 = n * SBS + kc + 2 * qcol;
                uint32_t bh0 = *(const uint32_t*)&sBhi[i0];
                uint32_t bh1 = *(const uint32_t*)&sBhi[i0 + 8];
                uint32_t bl0 = *(const uint32_t*)&sBlo[i0];
                uint32_t bl1 = *(const uint32_t*)&sBlo[i0 + 8];
#pragma unroll
                for (int mf = 0; mf < 2; mf++) {
                    mma_bf16(c[mf][nf], ah[mf][0], ah[mf][1], ah[mf][2], ah[mf][3], bh0, bh1);
                    mma_bf16(c[mf][nf], ah[mf][0], ah[mf][1], ah[mf][2], ah[mf][3], bl0, bl1);
                    mma_bf16(c[mf][nf], al[mf][0], al[mf][1], al[mf][2], al[mf][3], bh0, bh1);
                }
            }
        }
        __syncthreads();
    }

#pragma unroll
    for (int mf = 0; mf < 2; mf++) {
        int rbase = row0 + warpRow * 32 + mf * 16 + qrow;
        float sumA = 0.0f, sumB = 0.0f;
#pragma unroll
        for (int nf = 0; nf < 8; nf++) {
            int colp = col0 + warpCol * 64 + nf * 8 + 2 * qcol;
            float b0v = 0.f, b1v = 0.f;
            if (bias) { b0v = bias[colp]; b1v = bias[colp + 1]; }
            float f0 = c[mf][nf][0] + b0v;
            float f1 = c[mf][nf][1] + b1v;
            float f2 = c[mf][nf][2] + b0v;
            float f3 = c[mf][nf][3] + b1v;
            if (act) { f0 = silu_f(f0); f1 = silu_f(f1); f2 = silu_f(f2); f3 = silu_f(f3); }
            if (wout) {
                float w0v = __ldg(&wout[colp]);
                float w1v = __ldg(&wout[colp + 1]);
                sumA += f0 * w0v + f1 * w1v;
                sumB += f2 * w0v + f3 * w1v;
            } else if (outPacked) {
                uint32_t* Cp = (uint32_t*)Cout;
                if (rbase < Nrows)
                    *(uint2*)&Cp[(size_t)rbase * M + colp] =
                        make_uint2(pack_split(f0), pack_split(f1));
                if (rbase + 8 < Nrows)
                    *(uint2*)&Cp[(size_t)(rbase + 8) * M + colp] =
                        make_uint2(pack_split(f2), pack_split(f3));
            } else {
                float* Cf = (float*)Cout;
                if (rbase < Nrows)
                    *(float2*)&Cf[(size_t)rbase * M + colp] = make_float2(f0, f1);
                if (rbase + 8 < Nrows)
                    *(float2*)&Cf[(size_t)(rbase + 8) * M + colp] = make_float2(f2, f3);
            }
        }
        if (wout) {
            if (rbase < Nrows)     atomicAdd(&outv[rbase], sumA);
            if (rbase + 8 < Nrows) atomicAdd(&outv[rbase + 8], sumB);
        }
    }
}

// ---------------- hull kernel (unchanged, measured 331 us) ----------
#define HULL_SMEM_BYTES ((2 * 128 * HSBS + 2 * HTILE * HSAS) * 2 + (HTILE * 16 + 128) * 4)

__global__ __launch_bounds__(256, 2) void hull_kernel(
    const float* __restrict__ fea,
    const int* __restrict__ jidx, const int* __restrict__ iidx,
    const float* __restrict__ w0, const float* __restrict__ b0,
    const float* __restrict__ w1, const float* __restrict__ b1,
    const float* __restrict__ vhull, float* __restrict__ oh, int EHn)
{
    extern __shared__ char smraw[];
    __nv_bfloat16* s_w1hi  = (__nv_bfloat16*)smraw;
    __nv_bfloat16* s_w1lo  = s_w1hi + 128 * HSBS;
    __nv_bfloat16* s_hidhi = s_w1lo + 128 * HSBS;
    __nv_bfloat16* s_hidlo = s_hidhi + HTILE * HSAS;
    float* s_fea = (float*)(s_hidlo + HTILE * HSAS);
    float* s_b1  = s_fea + HTILE * 16;

    int tid = threadIdx.x;
    int wid = tid >> 5;
    int lane = tid & 31;
    int warpRow = wid & 1;
    int warpCol = wid >> 1;
    int qrow = lane >> 2;
    int qcol = lane & 3;
    int col = tid & 127;
    int wg  = tid >> 7;
    int g  = lane >> 3;
    int lr = lane & 7;

    for (int t = tid; t < 16384; t += 256) {
        int k = t >> 7, n = t & 127;
        float v = w1[t];
        __nv_bfloat16 h = __float2bfloat16(v);
        __nv_bfloat16 l = __float2bfloat16(v - __bfloat162float(h));
        s_w1hi[n * HSBS + k] = h;
        s_w1lo[n * HSBS + k] = l;
    }
    if (tid < 128) s_b1[tid] = b1[tid];
    float rw0[16];
#pragma unroll
    for (int k = 0; k < 16; k++) rw0[k] = w0[k * 128 + col];
    float rb0 = b0[col];

    uint32_t bHhi = smem_u32(s_hidhi), bHlo = smem_u32(s_hidlo);
    uint32_t bWhi = smem_u32(s_w1hi),  bWlo = smem_u32(s_w1lo);
    uint32_t aRowPart = (uint32_t)((warpRow * 16 + (g & 1) * 8 + lr) * HSAS * 2
                                   + (g >> 1) * 16);
    uint32_t bRowPart[2];
#pragma unroll
    for (int p = 0; p < 2; p++)
        bRowPart[p] = (uint32_t)(((warpCol * 32 + (2 * p + (g >> 1)) * 8 + lr) * HSBS
                                  + (g & 1) * 8) * 2);
    __syncthreads();

    for (int base = blockIdx.x * HTILE; base < EHn; base += gridDim.x * HTILE) {
        int ec = min(HTILE, EHn - base);

        for (int t = tid; t < ec * 16; t += 256)
            s_fea[t] = fea[(size_t)base * 16 + t];
        __syncthreads();

        int e0 = wg * 16, e1 = min(ec, e0 + 16);
        for (int e = e0; e < e1; e++) {
            float acc = rb0;
#pragma unroll
            for (int k = 0; k < 16; k++)
                acc += s_fea[e * 16 + k] * rw0[k];
            float hv = silu_f(acc);
            __nv_bfloat16 h = __float2bfloat16(hv);
            __nv_bfloat16 l = __float2bfloat16(hv - __bfloat162float(h));
            s_hidhi[e * HSAS + col] = h;
            s_hidlo[e * HSAS + col] = l;
        }
        __syncthreads();

        float c[4][4];
#pragma unroll
        for (int nf = 0; nf < 4; nf++)
#pragma unroll
            for (int q = 0; q < 4; q++) c[nf][q] = 0.0f;

#pragma unroll
        for (int kc = 0; kc < 128; kc += 16) {
            uint32_t kOff = kc * 2;
            uint32_t ah0, ah1, ah2, ah3, al0, al1, al2, al3;
            ldmx4(ah0, ah1, ah2, ah3, bHhi + aRowPart + kOff);
            ldmx4(al0, al1, al2, al3, bHlo + aRowPart + kOff);
#pragma unroll
            for (int p = 0; p < 2; p++) {
                uint32_t bh0, bh1, bh2, bh3, bl0, bl1, bl2, bl3;
                ldmx4(bh0, bh1, bh2, bh3, bWhi + bRowPart[p] + kOff);
                ldmx4(bl0, bl1, bl2, bl3, bWlo + bRowPart[p] + kOff);
                mma_bf16(c[2*p],   ah0, ah1, ah2, ah3, bh0, bh1);
                mma_bf16(c[2*p],   ah0, ah1, ah2, ah3, bl0, bl1);
                mma_bf16(c[2*p],   al0, al1, al2, al3, bh0, bh1);
                mma_bf16(c[2*p+1], ah0, ah1, ah2, ah3, bh2, bh3);
                mma_bf16(c[2*p+1], ah0, ah1, ah2, ah3, bl2, bl3);
                mma_bf16(c[2*p+1], al0, al1, al2, al3, bh2, bh3);
            }
        }

        int eA = warpRow * 16 + qrow;
        int eB = eA + 8;
        int jA = 0, iA = 0, jB = 0, iB = 0;
        bool vA = eA < ec, vB = eB < ec;
        if (vA) { jA = jidx[base + eA]; iA = iidx[base + eA]; }
        if (vB) { jB = jidx[base + eB]; iB = iidx[base + eB]; }
#pragma unroll
        for (int nf = 0; nf < 4; nf++) {
            int cp = warpCol * 32 + nf * 8 + 2 * qcol;
            float bb0 = s_b1[cp], bb1 = s_b1[cp + 1];
            if (vA) {
                float2 vh = *(const float2*)&vhull[(size_t)jA * 128 + cp];
                float f0 = (c[nf][0] + bb0) * vh.x;
                float f1 = (c[nf][1] + bb1) * vh.y;
                atomicAdd(&oh[(size_t)iA * 128 + cp], f0);
                atomicAdd(&oh[(size_t)iA * 128 + cp + 1], f1);
            }
            if (vB) {
                float2 vh = *(const float2*)&vhull[(size_t)jB * 128 + cp];
                float f2 = (c[nf][2] + bb0) * vh.x;
                float f3 = (c[nf][3] + bb1) * vh.y;
                atomicAdd(&oh[(size_t)iB * 128 + cp], f2);
                atomicAdd(&oh[(size_t)iB * 128 + cp + 1], f3);
            }
        }
        __syncthreads();
    }
}

// ---------------- launch ----------------
static void launch_gemm(const uint32_t* A0, int lda0, int ksplit,
                        const uint32_t* A1, int lda1,
                        const __nv_bfloat16* whiT, const __nv_bfloat16* wloT, int ldw,
                        const float* bias, void* C, int outPacked,
                        const float* wout, float* outv,
                        int N, int K, int M, int act)
{
    dim3 grid((N + 127) / 128, M / 128);
    gemm_mma<<<grid, 256>>>(A0, lda0, ksplit, A1, lda1, whiT, wloT, ldw,
                            bias, C, outPacked, wout, outv, N, K, M, act);
}

extern "C" void kernel_launch(void* const* d_in, const int* in_sizes, int n_in,
                              void* d_out, int out_size)
{
    const float* e2    = (const float*)d_in[0];
    const int*   iedge = (const int*)  d_in[1];
    const float* fea   = (const float*)d_in[2];
    const int*   eih   = (const int*)  d_in[3];
    const float* w_hull= (const float*)d_in[4];
    const float* w0    = (const float*)d_in[5];
    const float* b0    = (const float*)d_in[6];
    const float* w1    = (const float*)d_in[7];
    const float* b1    = (const float*)d_in[8];
    const float* w1h   = (const float*)d_in[9];
    const float* b1h   = (const float*)d_in[10];
    const float* w2h   = (const float*)d_in[11];
    const float* b2h   = (const float*)d_in[12];
    const float* wcat  = (const float*)d_in[13];
    const float* bcat  = (const float*)d_in[14];
    const float* wup   = (const float*)d_in[15];
    const float* bup   = (const float*)d_in[16];
    const float* wl0   = (const float*)d_in[17];
    const float* bl0   = (const float*)d_in[18];
    const float* wl1   = (const float*)d_in[19];
    const float* bl1   = (const float*)d_in[20];
    const float* wout  = (const float*)d_in[21];
    float* out = (float*)d_out;

    int N  = out_size;
    int E  = in_sizes[1];
    int EH = in_sizes[2] / 16;
    const int* jh = eih;
    const int* ih = eih + EH;

    float *pvh, *poh;
    uint32_t *pvp, *pohp, *pt128p, *pa256p, *pb256p;
    __nv_bfloat16 *pwhi, *pwlo;
    int *pcnt, *poff, *prun, *ppart, *peord;
    cudaGetSymbolAddress((void**)&pvh,    g_vhull);
    cudaGetSymbolAddress((void**)&poh,    g_oh);
    cudaGetSymbolAddress((void**)&pvp,    g_vp);
    cudaGetSymbolAddress((void**)&pohp,   g_ohp);
    cudaGetSymbolAddress((void**)&pt128p, g_t128p);
    cudaGetSymbolAddress((void**)&pa256p, g_a256p);
    cudaGetSymbolAddress((void**)&pb256p, g_b256p);
    cudaGetSymbolAddress((void**)&pwhi,   g_whi);
    cudaGetSymbolAddress((void**)&pwlo,   g_wlo);
    cudaGetSymbolAddress((void**)&pcnt,   g_counts);
    cudaGetSymbolAddress((void**)&poff,   g_offsets);
    cudaGetSymbolAddress((void**)&prun,   g_running);
    cudaGetSymbolAddress((void**)&ppart,  g_partial);
    cudaGetSymbolAddress((void**)&peord,  g_eorder);

    cudaFuncSetAttribute(hull_kernel, cudaFuncAttributeMaxDynamicSharedMemorySize,
                         HULL_SMEM_BYTES);
    cudaFuncSetAttribute(hull_kernel, cudaFuncAttributePreferredSharedMemoryCarveout,
                         100);

    // 0. pre-split weights into transposed bf16 planes
    {
        struct { const float* w; int off, K, M; } ws[7] = {
            { w_hull, OFF_WHULL, 128, 128 },
            { w1h,    OFF_W1H,   128, 128 },
            { w2h,    OFF_W2H,   128, 256 },
            { wcat,   OFF_WCAT,  384, 128 },
            { wup,    OFF_WUP,   128, 256 },
            { wl0,    OFF_WL0,   256, 256 },
            { wl1,    OFF_WL1,   256, 256 },
        };
        for (int i = 0; i < 7; i++) {
            int n = ws[i].K * ws[i].M;
            pack_weight_kernel<<<(n + 255) / 256, 256>>>(
                ws[i].w, pwhi + ws[i].off, pwlo + ws[i].off, ws[i].K, ws[i].M);
        }
    }

    // 1. zero oh + counts + out
    zero_kernel<<<2048, 256>>>(poh, pcnt, out, (size_t)N * 128, N);

    // 2. CSR build + segment-sum -> packed v
    int nb = (N + 1023) / 1024;
    hist_kernel<<<(E + 255) / 256, 256>>>(iedge, pcnt, E);
    scanA_kernel<<<nb, 1024>>>(pcnt, poff, ppart, N);
    scanB_kernel<<<1, 32>>>(ppart, nb);
    scanC_kernel<<<(N + 255) / 256, 256>>>(poff, ppart, prun, N);
    fill_kernel<<<(E + 255) / 256, 256>>>(iedge, prun, peord, E);
    csr_sum_kernel<<<(N * 32 + 255) / 256, 256>>>(
        (const float4*)e2, peord, poff, pcnt, pvp, N);

    // 3. v_hull = v @ w_hull (fp32 out for hull gather)
    launch_gemm(pvp, 128, 128, pvp, 128, pwhi + OFF_WHULL, pwlo + OFF_WHULL, 128,
                nullptr, pvh, 0, nullptr, nullptr, N, 128, 128, 0);

    // 4. hull message passing; pack oh
    hull_kernel<<<296, 256, HULL_SMEM_BYTES>>>(
        fea, jh, ih, w0, b0, w1, b1, pvh, poh, EH);
    pack_act_kernel<<<2048, 256>>>(poh, pohp, (size_t)N * 128);

    // 5. t128p = silu(oh @ w1_hull + b1_hull)
    launch_gemm(pohp, 128, 128, pohp, 128, pwhi + OFF_W1H, pwlo + OFF_W1H, 128,
                b1h, pt128p, 1, nullptr, nullptr, N, 128, 128, 1);
    // 6. a256p = t128 @ w2_hull + b2_hull
    launch_gemm(pt128p, 128, 128, pt128p, 128, pwhi + OFF_W2H, pwlo + OFF_W2H, 128,
                b2h, pa256p, 1, nullptr, nullptr, N, 128, 256, 0);
    // 7. t128p = silu([v | a256] @ w_cat + b_cat)   (K = 384)
    launch_gemm(pvp, 128, 128, pa256p, 256, pwhi + OFF_WCAT, pwlo + OFF_WCAT, 384,
                bcat, pt128p, 1, nullptr, nullptr, N, 384, 128, 1);
    // 8. b256p = t128 @ w_up + b_up
    launch_gemm(pt128p, 128, 128, pt128p, 128, pwhi + OFF_WUP, pwlo + OFF_WUP, 128,
                bup, pb256p, 1, nullptr, nullptr, N, 128, 256, 0);
    // 9. a256p = silu(b256 @ w_l0 + b_l0)
    launch_gemm(pb256p, 256, 256, pb256p, 256, pwhi + OFF_WL0, pwlo + OFF_WL0, 256,
                bl0, pa256p, 1, nullptr, nullptr, N, 256, 256, 1);
    // 10+11 fused: out += silu(a256 @ w_l1 + b_l1) . w_out
    launch_gemm(pa256p, 256, 256, pa256p, 256, pwhi + OFF_WL1, pwlo + OFF_WL1, 256,
                bl1, nullptr, 0, wout, out, N, 256, 256, 1);
}

// round 14
// speedup vs baseline: 1.1630x; 1.0248x over previous
#include <cuda_runtime.h>
#include <cuda_bf16.h>
#include <math.h>
#include <stdint.h>

#define NMAX 100000
#define EMAX 1000000
#define EHMAX 500000
#define KBLK 32
#define HTILE 32
#define SAS 40
#define SBS 42
#define HSAS 136
#define HSBS 136

// weight-plane offsets (bf16 elements, transposed [M][K])
#define OFF_WHULL 0
#define OFF_W1H   16384
#define OFF_W2H   32768
#define OFF_WCAT  65536
#define OFF_WUP   114688
#define OFF_WL0   147456
#define OFF_WL1   212992
#define WPLANE_TOTAL 278528

// ---------------- scratch ----------------
__device__ float    g_vhull[(size_t)NMAX * 128];
__device__ float    g_ehull[(size_t)EHMAX * 128];
__device__ uint32_t g_vp   [(size_t)NMAX * 128];
__device__ uint32_t g_ohp  [(size_t)NMAX * 128];
__device__ uint32_t g_t128p[(size_t)NMAX * 128];
__device__ uint32_t g_a256p[(size_t)NMAX * 256];
__device__ uint32_t g_b256p[(size_t)NMAX * 256];
__device__ __nv_bfloat16 g_whi[WPLANE_TOTAL];
__device__ __nv_bfloat16 g_wlo[WPLANE_TOTAL];
// CSR scratch (main graph)
__device__ int g_counts [NMAX];
__device__ int g_offsets[NMAX];
__device__ int g_running[NMAX];
__device__ int g_partial[128];
__device__ int g_eorder [EMAX];
// CSR scratch (hull graph)
__device__ int g_counts2 [NMAX];
__device__ int g_offsets2[NMAX];
__device__ int g_running2[NMAX];
__device__ int g_partial2[128];
__device__ int g_pos     [EHMAX];

__device__ __forceinline__ float silu_f(float x) { return x / (1.0f + expf(-x)); }

__device__ __forceinline__ uint32_t smem_u32(const void* p) {
    uint32_t a;
    asm("{ .reg .u64 t; cvta.to.shared.u64 t, %1; cvt.u32.u64 %0, t; }" : "=r"(a) : "l"(p));
    return a;
}

__device__ __forceinline__ void mma_bf16(float* c, uint32_t a0, uint32_t a1,
                                         uint32_t a2, uint32_t a3,
                                         uint32_t b0, uint32_t b1) {
    asm volatile(
        "mma.sync.aligned.m16n8k16.row.col.f32.bf16.bf16.f32 "
        "{%0,%1,%2,%3}, {%4,%5,%6,%7}, {%8,%9}, {%0,%1,%2,%3};"
        : "+f"(c[0]), "+f"(c[1]), "+f"(c[2]), "+f"(c[3])
        : "r"(a0), "r"(a1), "r"(a2), "r"(a3), "r"(b0), "r"(b1));
}

__device__ __forceinline__ void ldmx4(uint32_t& r0, uint32_t& r1,
                                      uint32_t& r2, uint32_t& r3, uint32_t addr) {
    asm volatile("ldmatrix.sync.aligned.m8n8.x4.shared.b16 {%0,%1,%2,%3}, [%4];"
                 : "=r"(r0), "=r"(r1), "=r"(r2), "=r"(r3) : "r"(addr));
}

__device__ __forceinline__ uint32_t pack_split(float f) {
    __nv_bfloat16 h = __float2bfloat16(f);
    __nv_bfloat16 l = __float2bfloat16(f - __bfloat162float(h));
    return (uint32_t)__bfloat16_as_ushort(h) | ((uint32_t)__bfloat16_as_ushort(l) << 16);
}

// ---------------- prep kernels ----------------
__global__ void pack_weight_kernel(const float* __restrict__ W,
                                   __nv_bfloat16* __restrict__ hiT,
                                   __nv_bfloat16* __restrict__ loT, int K, int M)
{
    int idx = blockIdx.x * blockDim.x + threadIdx.x;
    if (idx >= K * M) return;
    int k = idx / M, m = idx % M;
    float v = W[idx];
    __nv_bfloat16 h = __float2bfloat16(v);
    __nv_bfloat16 l = __float2bfloat16(v - __bfloat162float(h));
    hiT[(size_t)m * K + k] = h;
    loT[(size_t)m * K + k] = l;
}

// ---------------- zero counts (both graphs) + out ----------------
__global__ void zero_kernel(int* counts, int* counts2, float* outv, int N)
{
    int t = blockIdx.x * blockDim.x + threadIdx.x;
    int stride = gridDim.x * blockDim.x;
    for (int x = t; x < N; x += stride) { counts[x] = 0; counts2[x] = 0; outv[x] = 0.0f; }
}

// ---------------- CSR build ----------------
__global__ void hist_kernel(const int* __restrict__ idx, int* __restrict__ counts, int E)
{
    int e = blockIdx.x * blockDim.x + threadIdx.x;
    if (e < E) atomicAdd(&counts[idx[e]], 1);
}

__global__ void scanA_kernel(const int* __restrict__ counts,
                             int* __restrict__ offsets,
                             int* __restrict__ partial, int N)
{
    __shared__ int s[1024];
    int t = threadIdx.x;
    int i = blockIdx.x * 1024 + t;
    int v = (i < N) ? counts[i] : 0;
    s[t] = v;
    __syncthreads();
#pragma unroll
    for (int o = 1; o < 1024; o <<= 1) {
        int x = (t >= o) ? s[t - o] : 0;
        __syncthreads();
        s[t] += x;
        __syncthreads();
    }
    if (i < N) offsets[i] = s[t] - v;
    if (t == 1023) partial[blockIdx.x] = s[1023];
}

__global__ void scanB_kernel(int* __restrict__ partial, int nb)
{
    if (threadIdx.x == 0 && blockIdx.x == 0) {
        int run = 0;
        for (int i = 0; i < nb; i++) { int t = partial[i]; partial[i] = run; run += t; }
    }
}

__global__ void scanC_kernel(int* __restrict__ offsets,
                             const int* __restrict__ partial,
                             int* __restrict__ running, int N)
{
    int i = blockIdx.x * blockDim.x + threadIdx.x;
    if (i < N) {
        int o = offsets[i] + partial[i >> 10];
        offsets[i] = o;
        running[i] = o;
    }
}

__global__ void fill_kernel(const int* __restrict__ idx,
                            int* __restrict__ running,
                            int* __restrict__ eorder, int E)
{
    int e = blockIdx.x * blockDim.x + threadIdx.x;
    if (e < E) {
        int slot = atomicAdd(&running[idx[e]], 1);
        eorder[slot] = e;
    }
}

__global__ void fill_pos_kernel(const int* __restrict__ idx,
                                int* __restrict__ running,
                                int* __restrict__ pos, int E)
{
    int e = blockIdx.x * blockDim.x + threadIdx.x;
    if (e < E) {
        int slot = atomicAdd(&running[idx[e]], 1);
        pos[e] = slot;
    }
}

// warp per node: sequential sum of its edges' rows; writes packed v directly
__global__ void csr_sum_kernel(const float4* __restrict__ e2,
                               const int* __restrict__ eorder,
                               const int* __restrict__ offsets,
                               const int* __restrict__ counts,
                               uint32_t* __restrict__ vp, int N)
{
    int gwarp = (blockIdx.x * blockDim.x + threadIdx.x) >> 5;
    int lane = threadIdx.x & 31;
    if (gwarp >= N) return;
    int beg = offsets[gwarp];
    int end = beg + counts[gwarp];
    float4 acc = make_float4(0.f, 0.f, 0.f, 0.f);
    for (int k = beg; k < end; k++) {
        int row = eorder[k];
        float4 v = e2[(size_t)row * 32 + lane];
        acc.x += v.x; acc.y += v.y; acc.z += v.z; acc.w += v.w;
    }
    uint4 o;
    o.x = pack_split(acc.x); o.y = pack_split(acc.y);
    o.z = pack_split(acc.z); o.w = pack_split(acc.w);
    *(uint4*)&vp[(size_t)gwarp * 128 + lane * 4] = o;
}

// warp per node: sum CONTIGUOUS ehull rows [off, off+cnt); write packed ohp
__global__ void hull_reduce_kernel(const float4* __restrict__ ehull,
                                   const int* __restrict__ offsets,
                                   const int* __restrict__ counts,
                                   uint32_t* __restrict__ ohp, int N)
{
    int gwarp = (blockIdx.x * blockDim.x + threadIdx.x) >> 5;
    int lane = threadIdx.x & 31;
    if (gwarp >= N) return;
    int beg = offsets[gwarp];
    int end = beg + counts[gwarp];
    float4 acc = make_float4(0.f, 0.f, 0.f, 0.f);
    for (int r = beg; r < end; r++) {
        float4 v = ehull[(size_t)r * 32 + lane];
        acc.x += v.x; acc.y += v.y; acc.z += v.z; acc.w += v.w;
    }
    uint4 o;
    o.x = pack_split(acc.x); o.y = pack_split(acc.y);
    o.z = pack_split(acc.z); o.w = pack_split(acc.w);
    *(uint4*)&ohp[(size_t)gwarp * 128 + lane * 4] = o;
}

// ---------------- warp-MMA bf16 split-3 GEMM (R10 proven core) ----------------
__global__ __launch_bounds__(256, 2) void gemm_mma(
    const uint32_t* __restrict__ A0, int lda0, int ksplit,
    const uint32_t* __restrict__ A1, int lda1,
    const __nv_bfloat16* __restrict__ WhiT, const __nv_bfloat16* __restrict__ WloT,
    int ldw, const float* __restrict__ bias,
    void* __restrict__ Cout, int outPacked,
    const float* __restrict__ wout, float* __restrict__ outv,
    int Nrows, int K, int M, int act)
{
    __shared__ __nv_bfloat16 sAhi[128 * SAS];
    __shared__ __nv_bfloat16 sAlo[128 * SAS];
    __shared__ __nv_bfloat16 sBhi[128 * SBS];
    __shared__ __nv_bfloat16 sBlo[128 * SBS];

    int tid = threadIdx.x;
    int wid = tid >> 5;
    int lane = tid & 31;
    int warpRow = wid & 3;
    int warpCol = wid >> 2;
    int row0 = blockIdx.x * 128;
    int col0 = blockIdx.y * 128;

    float c[2][8][4];
#pragma unroll
    for (int mf = 0; mf < 2; mf++)
#pragma unroll
        for (int nf = 0; nf < 8; nf++)
#pragma unroll
            for (int q = 0; q < 4; q++) c[mf][nf][q] = 0.0f;

    int qrow = lane >> 2;
    int qcol = lane & 3;

    for (int k0 = 0; k0 < K; k0 += KBLK) {
        const uint32_t* srcA;
        int kbase, ld;
        if (k0 < ksplit) { srcA = A0; kbase = k0; ld = lda0; }
        else             { srcA = A1; kbase = k0 - ksplit; ld = lda1; }
#pragma unroll
        for (int it = 0; it < 4; it++) {
            int idx = tid + it * 256;
            int r = idx >> 3;
            int kq = (idx & 7) * 4;
            uint4 u = make_uint4(0u, 0u, 0u, 0u);
            int grow = row0 + r;
            if (grow < Nrows)
                u = *(const uint4*)&srcA[(size_t)grow * ld + kbase + kq];
            uint32_t hi01 = __byte_perm(u.x, u.y, 0x5410);
            uint32_t lo01 = __byte_perm(u.x, u.y, 0x7632);
            uint32_t hi23 = __byte_perm(u.z, u.w, 0x5410);
            uint32_t lo23 = __byte_perm(u.z, u.w, 0x7632);
            int base = r * SAS + kq;
            *(uint2*)&sAhi[base] = make_uint2(hi01, hi23);
            *(uint2*)&sAlo[base] = make_uint2(lo01, lo23);
        }
#pragma unroll
        for (int it = 0; it < 4; it++) {
            int idx = tid + it * 256;
            int n = idx >> 3;
            int kq = (idx & 7) * 4;
            size_t goff = (size_t)(col0 + n) * ldw + k0 + kq;
            uint2 uh = *(const uint2*)&WhiT[goff];
            uint2 ul = *(const uint2*)&WloT[goff];
            int b = n * SBS + kq;
            *(uint32_t*)&sBhi[b]     = uh.x;
            *(uint32_t*)&sBhi[b + 2] = uh.y;
            *(uint32_t*)&sBlo[b]     = ul.x;
            *(uint32_t*)&sBlo[b + 2] = ul.y;
        }
        __syncthreads();

#pragma unroll
        for (int kc = 0; kc < KBLK; kc += 16) {
            uint32_t ah[2][4], al[2][4];
#pragma unroll
            for (int mf = 0; mf < 2; mf++) {
                int r = warpRow * 32 + mf * 16 + qrow;
                int i0 = r * SAS + kc + 2 * qcol;
                ah[mf][0] = *(const uint32_t*)&sAhi[i0];
                ah[mf][1] = *(const uint32_t*)&sAhi[i0 + 8 * SAS];
                ah[mf][2] = *(const uint32_t*)&sAhi[i0 + 8];
                ah[mf][3] = *(const uint32_t*)&sAhi[i0 + 8 * SAS + 8];
                al[mf][0] = *(const uint32_t*)&sAlo[i0];
                al[mf][1] = *(const uint32_t*)&sAlo[i0 + 8 * SAS];
                al[mf][2] = *(const uint32_t*)&sAlo[i0 + 8];
                al[mf][3] = *(const uint32_t*)&sAlo[i0 + 8 * SAS + 8];
            }
#pragma unroll
            for (int nf = 0; nf < 8; nf++) {
                int n = warpCol * 64 + nf * 8 + qrow;
                int i0 = n * SBS + kc + 2 * qcol;
                uint32_t bh0 = *(const uint32_t*)&sBhi[i0];
                uint32_t bh1 = *(const uint32_t*)&sBhi[i0 + 8];
                uint32_t bl0 = *(const uint32_t*)&sBlo[i0];
                uint32_t bl1 = *(const uint32_t*)&sBlo[i0 + 8];
#pragma unroll
                for (int mf = 0; mf < 2; mf++) {
                    mma_bf16(c[mf][nf], ah[mf][0], ah[mf][1], ah[mf][2], ah[mf][3], bh0, bh1);
                    mma_bf16(c[mf][nf], ah[mf][0], ah[mf][1], ah[mf][2], ah[mf][3], bl0, bl1);
                    mma_bf16(c[mf][nf], al[mf][0], al[mf][1], al[mf][2], al[mf][3], bh0, bh1);
                }
            }
        }
        __syncthreads();
    }

#pragma unroll
    for (int mf = 0; mf < 2; mf++) {
        int rbase = row0 + warpRow * 32 + mf * 16 + qrow;
        float sumA = 0.0f, sumB = 0.0f;
#pragma unroll
        for (int nf = 0; nf < 8; nf++) {
            int colp = col0 + warpCol * 64 + nf * 8 + 2 * qcol;
            float b0v = 0.f, b1v = 0.f;
            if (bias) { b0v = bias[colp]; b1v = bias[colp + 1]; }
            float f0 = c[mf][nf][0] + b0v;
            float f1 = c[mf][nf][1] + b1v;
            float f2 = c[mf][nf][2] + b0v;
            float f3 = c[mf][nf][3] + b1v;
            if (act) { f0 = silu_f(f0); f1 = silu_f(f1); f2 = silu_f(f2); f3 = silu_f(f3); }
            if (wout) {
                float w0v = __ldg(&wout[colp]);
                float w1v = __ldg(&wout[colp + 1]);
                sumA += f0 * w0v + f1 * w1v;
                sumB += f2 * w0v + f3 * w1v;
            } else if (outPacked) {
                uint32_t* Cp = (uint32_t*)Cout;
                if (rbase < Nrows)
                    *(uint2*)&Cp[(size_t)rbase * M + colp] =
                        make_uint2(pack_split(f0), pack_split(f1));
                if (rbase + 8 < Nrows)
                    *(uint2*)&Cp[(size_t)(rbase + 8) * M + colp] =
                        make_uint2(pack_split(f2), pack_split(f3));
            } else {
                float* Cf = (float*)Cout;
                if (rbase < Nrows)
                    *(float2*)&Cf[(size_t)rbase * M + colp] = make_float2(f0, f1);
                if (rbase + 8 < Nrows)
                    *(float2*)&Cf[(size_t)(rbase + 8) * M + colp] = make_float2(f2, f3);
            }
        }
        if (wout) {
            if (rbase < Nrows)     atomicAdd(&outv[rbase], sumA);
            if (rbase + 8 < Nrows) atomicAdd(&outv[rbase + 8], sumB);
        }
    }
}

// ---------------- hull kernel: MLP + MMA + gather, STG to CSR slots ----------
#define HULL_SMEM_BYTES ((2 * 128 * HSBS + 2 * HTILE * HSAS) * 2 + (HTILE * 16 + 128) * 4)

__global__ __launch_bounds__(256, 2) void hull_kernel(
    const float* __restrict__ fea,
    const int* __restrict__ jidx, const int* __restrict__ pos,
    const float* __restrict__ w0, const float* __restrict__ b0,
    const float* __restrict__ w1, const float* __restrict__ b1,
    const float* __restrict__ vhull, float* __restrict__ ehull, int EHn)
{
    extern __shared__ char smraw[];
    __nv_bfloat16* s_w1hi  = (__nv_bfloat16*)smraw;
    __nv_bfloat16* s_w1lo  = s_w1hi + 128 * HSBS;
    __nv_bfloat16* s_hidhi = s_w1lo + 128 * HSBS;
    __nv_bfloat16* s_hidlo = s_hidhi + HTILE * HSAS;
    float* s_fea = (float*)(s_hidlo + HTILE * HSAS);
    float* s_b1  = s_fea + HTILE * 16;

    int tid = threadIdx.x;
    int wid = tid >> 5;
    int lane = tid & 31;
    int warpRow = wid & 1;
    int warpCol = wid >> 1;
    int qrow = lane >> 2;
    int qcol = lane & 3;
    int col = tid & 127;
    int wg  = tid >> 7;
    int g  = lane >> 3;
    int lr = lane & 7;

    for (int t = tid; t < 16384; t += 256) {
        int k = t >> 7, n = t & 127;
        float v = w1[t];
        __nv_bfloat16 h = __float2bfloat16(v);
        __nv_bfloat16 l = __float2bfloat16(v - __bfloat162float(h));
        s_w1hi[n * HSBS + k] = h;
        s_w1lo[n * HSBS + k] = l;
    }
    if (tid < 128) s_b1[tid] = b1[tid];
    float rw0[16];
#pragma unroll
    for (int k = 0; k < 16; k++) rw0[k] = w0[k * 128 + col];
    float rb0 = b0[col];

    uint32_t bHhi = smem_u32(s_hidhi), bHlo = smem_u32(s_hidlo);
    uint32_t bWhi = smem_u32(s_w1hi),  bWlo = smem_u32(s_w1lo);
    uint32_t aRowPart = (uint32_t)((warpRow * 16 + (g & 1) * 8 + lr) * HSAS * 2
                                   + (g >> 1) * 16);
    uint32_t bRowPart[2];
#pragma unroll
    for (int p = 0; p < 2; p++)
        bRowPart[p] = (uint32_t)(((warpCol * 32 + (2 * p + (g >> 1)) * 8 + lr) * HSBS
                                  + (g & 1) * 8) * 2);
    __syncthreads();

    for (int base = blockIdx.x * HTILE; base < EHn; base += gridDim.x * HTILE) {
        int ec = min(HTILE, EHn - base);

        for (int t = tid; t < ec * 16; t += 256)
            s_fea[t] = fea[(size_t)base * 16 + t];
        __syncthreads();

        int e0 = wg * 16, e1 = min(ec, e0 + 16);
        for (int e = e0; e < e1; e++) {
            float acc = rb0;
#pragma unroll
            for (int k = 0; k < 16; k++)
                acc += s_fea[e * 16 + k] * rw0[k];
            float hv = silu_f(acc);
            __nv_bfloat16 h = __float2bfloat16(hv);
            __nv_bfloat16 l = __float2bfloat16(hv - __bfloat162float(h));
            s_hidhi[e * HSAS + col] = h;
            s_hidlo[e * HSAS + col] = l;
        }
        __syncthreads();

        float c[4][4];
#pragma unroll
        for (int nf = 0; nf < 4; nf++)
#pragma unroll
            for (int q = 0; q < 4; q++) c[nf][q] = 0.0f;

#pragma unroll
        for (int kc = 0; kc < 128; kc += 16) {
            uint32_t kOff = kc * 2;
            uint32_t ah0, ah1, ah2, ah3, al0, al1, al2, al3;
            ldmx4(ah0, ah1, ah2, ah3, bHhi + aRowPart + kOff);
            ldmx4(al0, al1, al2, al3, bHlo + aRowPart + kOff);
#pragma unroll
            for (int p = 0; p < 2; p++) {
                uint32_t bh0, bh1, bh2, bh3, bl0, bl1, bl2, bl3;
                ldmx4(bh0, bh1, bh2, bh3, bWhi + bRowPart[p] + kOff);
                ldmx4(bl0, bl1, bl2, bl3, bWlo + bRowPart[p] + kOff);
                mma_bf16(c[2*p],   ah0, ah1, ah2, ah3, bh0, bh1);
                mma_bf16(c[2*p],   ah0, ah1, ah2, ah3, bl0, bl1);
                mma_bf16(c[2*p],   al0, al1, al2, al3, bh0, bh1);
                mma_bf16(c[2*p+1], ah0, ah1, ah2, ah3, bh2, bh3);
                mma_bf16(c[2*p+1], ah0, ah1, ah2, ah3, bl2, bl3);
                mma_bf16(c[2*p+1], al0, al1, al2, al3, bh2, bh3);
            }
        }

        // epilogue: gather-multiply, STG to CSR slot rows (no atomics)
        int eA = warpRow * 16 + qrow;
        int eB = eA + 8;
        int jA = 0, sA = 0, jB = 0, sB = 0;
        bool vA = eA < ec, vB = eB < ec;
        if (vA) { jA = jidx[base + eA]; sA = pos[base + eA]; }
        if (vB) { jB = jidx[base + eB]; sB = pos[base + eB]; }
#pragma unroll
        for (int nf = 0; nf < 4; nf++) {
            int cp = warpCol * 32 + nf * 8 + 2 * qcol;
            float bb0 = s_b1[cp], bb1 = s_b1[cp + 1];
            if (vA) {
                float2 vh = *(const float2*)&vhull[(size_t)jA * 128 + cp];
                *(float2*)&ehull[(size_t)sA * 128 + cp] =
                    make_float2((c[nf][0] + bb0) * vh.x, (c[nf][1] + bb1) * vh.y);
            }
            if (vB) {
                float2 vh = *(const float2*)&vhull[(size_t)jB * 128 + cp];
                *(float2*)&ehull[(size_t)sB * 128 + cp] =
                    make_float2((c[nf][2] + bb0) * vh.x, (c[nf][3] + bb1) * vh.y);
            }
        }
        __syncthreads();
    }
}

// ---------------- launch ----------------
static void launch_gemm(const uint32_t* A0, int lda0, int ksplit,
                        const uint32_t* A1, int lda1,
                        const __nv_bfloat16* whiT, const __nv_bfloat16* wloT, int ldw,
                        const float* bias, void* C, int outPacked,
                        const float* wout, float* outv,
                        int N, int K, int M, int act)
{
    dim3 grid((N + 127) / 128, M / 128);
    gemm_mma<<<grid, 256>>>(A0, lda0, ksplit, A1, lda1, whiT, wloT, ldw,
                            bias, C, outPacked, wout, outv, N, K, M, act);
}

extern "C" void kernel_launch(void* const* d_in, const int* in_sizes, int n_in,
                              void* d_out, int out_size)
{
    const float* e2    = (const float*)d_in[0];
    const int*   iedge = (const int*)  d_in[1];
    const float* fea   = (const float*)d_in[2];
    const int*   eih   = (const int*)  d_in[3];
    const float* w_hull= (const float*)d_in[4];
    const float* w0    = (const float*)d_in[5];
    const float* b0    = (const float*)d_in[6];
    const float* w1    = (const float*)d_in[7];
    const float* b1    = (const float*)d_in[8];
    const float* w1h   = (const float*)d_in[9];
    const float* b1h   = (const float*)d_in[10];
    const float* w2h   = (const float*)d_in[11];
    const float* b2h   = (const float*)d_in[12];
    const float* wcat  = (const float*)d_in[13];
    const float* bcat  = (const float*)d_in[14];
    const float* wup   = (const float*)d_in[15];
    const float* bup   = (const float*)d_in[16];
    const float* wl0   = (const float*)d_in[17];
    const float* bl0   = (const float*)d_in[18];
    const float* wl1   = (const float*)d_in[19];
    const float* bl1   = (const float*)d_in[20];
    const float* wout  = (const float*)d_in[21];
    float* out = (float*)d_out;

    int N  = out_size;
    int E  = in_sizes[1];
    int EH = in_sizes[2] / 16;
    const int* jh = eih;
    const int* ih = eih + EH;

    float *pvh, *peh;
    uint32_t *pvp, *pohp, *pt128p, *pa256p, *pb256p;
    __nv_bfloat16 *pwhi, *pwlo;
    int *pcnt, *poff, *prun, *ppart, *peord;
    int *pcnt2, *poff2, *prun2, *ppart2, *ppos;
    cudaGetSymbolAddress((void**)&pvh,    g_vhull);
    cudaGetSymbolAddress((void**)&peh,    g_ehull);
    cudaGetSymbolAddress((void**)&pvp,    g_vp);
    cudaGetSymbolAddress((void**)&pohp,   g_ohp);
    cudaGetSymbolAddress((void**)&pt128p, g_t128p);
    cudaGetSymbolAddress((void**)&pa256p, g_a256p);
    cudaGetSymbolAddress((void**)&pb256p, g_b256p);
    cudaGetSymbolAddress((void**)&pwhi,   g_whi);
    cudaGetSymbolAddress((void**)&pwlo,   g_wlo);
    cudaGetSymbolAddress((void**)&pcnt,   g_counts);
    cudaGetSymbolAddress((void**)&poff,   g_offsets);
    cudaGetSymbolAddress((void**)&prun,   g_running);
    cudaGetSymbolAddress((void**)&ppart,  g_partial);
    cudaGetSymbolAddress((void**)&peord,  g_eorder);
    cudaGetSymbolAddress((void**)&pcnt2,  g_counts2);
    cudaGetSymbolAddress((void**)&poff2,  g_offsets2);
    cudaGetSymbolAddress((void**)&prun2,  g_running2);
    cudaGetSymbolAddress((void**)&ppart2, g_partial2);
    cudaGetSymbolAddress((void**)&ppos,   g_pos);

    cudaFuncSetAttribute(hull_kernel, cudaFuncAttributeMaxDynamicSharedMemorySize,
                         HULL_SMEM_BYTES);
    cudaFuncSetAttribute(hull_kernel, cudaFuncAttributePreferredSharedMemoryCarveout,
                         100);

    // 0. pre-split weights into transposed bf16 planes
    {
        struct { const float* w; int off, K, M; } ws[7] = {
            { w_hull, OFF_WHULL, 128, 128 },
            { w1h,    OFF_W1H,   128, 128 },
            { w2h,    OFF_W2H,   128, 256 },
            { wcat,   OFF_WCAT,  384, 128 },
            { wup,    OFF_WUP,   128, 256 },
            { wl0,    OFF_WL0,   256, 256 },
            { wl1,    OFF_WL1,   256, 256 },
        };
        for (int i = 0; i < 7; i++) {
            int n = ws[i].K * ws[i].M;
            pack_weight_kernel<<<(n + 255) / 256, 256>>>(
                ws[i].w, pwhi + ws[i].off, pwlo + ws[i].off, ws[i].K, ws[i].M);
        }
    }

    // 1. zero counts (both) + out
    zero_kernel<<<512, 256>>>(pcnt, pcnt2, out, N);

    // 2. CSR build (main graph) + segment-sum -> packed v
    int nb = (N + 1023) / 1024;
    hist_kernel<<<(E + 255) / 256, 256>>>(iedge, pcnt, E);
    scanA_kernel<<<nb, 1024>>>(pcnt, poff, ppart, N);
    scanB_kernel<<<1, 32>>>(ppart, nb);
    scanC_kernel<<<(N + 255) / 256, 256>>>(poff, ppart, prun, N);
    fill_kernel<<<(E + 255) / 256, 256>>>(iedge, prun, peord, E);
    csr_sum_kernel<<<(N * 32 + 255) / 256, 256>>>(
        (const float4*)e2, peord, poff, pcnt, pvp, N);

    // 2b. CSR build (hull graph, destinations ih) -> pos
    hist_kernel<<<(EH + 255) / 256, 256>>>(ih, pcnt2, EH);
    scanA_kernel<<<nb, 1024>>>(pcnt2, poff2, ppart2, N);
    scanB_kernel<<<1, 32>>>(ppart2, nb);
    scanC_kernel<<<(N + 255) / 256, 256>>>(poff2, ppart2, prun2, N);
    fill_pos_kernel<<<(EH + 255) / 256, 256>>>(ih, prun2, ppos, EH);

    // 3. v_hull = v @ w_hull (fp32 out for hull gather)
    launch_gemm(pvp, 128, 128, pvp, 128, pwhi + OFF_WHULL, pwlo + OFF_WHULL, 128,
                nullptr, pvh, 0, nullptr, nullptr, N, 128, 128, 0);

    // 4. hull message passing (STG to slots) + reduce -> packed ohp
    hull_kernel<<<296, 256, HULL_SMEM_BYTES>>>(
        fea, jh, ppos, w0, b0, w1, b1, pvh, peh, EH);
    hull_reduce_kernel<<<(N * 32 + 255) / 256, 256>>>(
        (const float4*)peh, poff2, pcnt2, pohp, N);

    // 5. t128p = silu(oh @ w1_hull + b1_hull)
    launch_gemm(pohp, 128, 128, pohp, 128, pwhi + OFF_W1H, pwlo + OFF_W1H, 128,
                b1h, pt128p, 1, nullptr, nullptr, N, 128, 128, 1);
    // 6. a256p = t128 @ w2_hull + b2_hull
    launch_gemm(pt128p, 128, 128, pt128p, 128, pwhi + OFF_W2H, pwlo + OFF_W2H, 128,
                b2h, pa256p, 1, nullptr, nullptr, N, 128, 256, 0);
    // 7. t128p = silu([v | a256] @ w_cat + b_cat)   (K = 384)
    launch_gemm(pvp, 128, 128, pa256p, 256, pwhi + OFF_WCAT, pwlo + OFF_WCAT, 384,
                bcat, pt128p, 1, nullptr, nullptr, N, 384, 128, 1);
    // 8. b256p = t128 @ w_up + b_up
    launch_gemm(pt128p, 128, 128, pt128p, 128, pwhi + OFF_WUP, pwlo + OFF_WUP, 128,
                bup, pb256p, 1, nullptr, nullptr, N, 128, 256, 0);
    // 9. a256p = silu(b256 @ w_l0 + b_l0)
    launch_gemm(pb256p, 256, 256, pb256p, 256, pwhi + OFF_WL0, pwlo + OFF_WL0, 256,
                bl0, pa256p, 1, nullptr, nullptr, N, 256, 256, 1);
    // 10+11 fused: out += silu(a256 @ w_l1 + b_l1) . w_out
    launch_gemm(pa256p, 256, 256, pa256p, 256, pwhi + OFF_WL1, pwlo + OFF_WL1, 256,
                bl1, nullptr, 0, wout, out, N, 256, 256, 1);
}

// round 15
// speedup vs baseline: 1.1928x; 1.0256x over previous
#include <cuda_runtime.h>
#include <cuda_bf16.h>
#include <math.h>
#include <stdint.h>

#define NMAX 100000
#define EMAX 1000000
#define EHMAX 500000
#define KBLK 32
#define HTILE 32
#define SAS 40
#define SBS 42
#define HSAS 136
#define HSBS 136

// weight-plane offsets (bf16 elements, transposed [M][K])
#define OFF_WHULL 0
#define OFF_W1H   16384
#define OFF_W2H   32768
#define OFF_WCAT  65536
#define OFF_WUP   114688
#define OFF_WL0   147456
#define OFF_WL1   212992
#define WPLANE_TOTAL 278528

// ---------------- scratch ----------------
__device__ float    g_vhull[(size_t)NMAX * 128];
__device__ float    g_ehull[(size_t)EHMAX * 128];
__device__ uint32_t g_vp   [(size_t)NMAX * 128];
__device__ uint32_t g_ohp  [(size_t)NMAX * 128];
__device__ uint32_t g_t128p[(size_t)NMAX * 128];
__device__ uint32_t g_a256p[(size_t)NMAX * 256];
__device__ uint32_t g_b256p[(size_t)NMAX * 256];
__device__ __nv_bfloat16 g_whi[WPLANE_TOTAL];
__device__ __nv_bfloat16 g_wlo[WPLANE_TOTAL];
// CSR scratch (main graph)
__device__ int g_counts [NMAX];
__device__ int g_offsets[NMAX];
__device__ int g_running[NMAX];
__device__ int g_partial[128];
__device__ int g_eorder [EMAX];
// CSR scratch (hull graph)
__device__ int g_counts2 [NMAX];
__device__ int g_offsets2[NMAX];
__device__ int g_running2[NMAX];
__device__ int g_partial2[128];
__device__ int g_pos     [EHMAX];

__device__ __forceinline__ float silu_f(float x) { return x / (1.0f + expf(-x)); }

__device__ __forceinline__ uint32_t smem_u32(const void* p) {
    uint32_t a;
    asm("{ .reg .u64 t; cvta.to.shared.u64 t, %1; cvt.u32.u64 %0, t; }" : "=r"(a) : "l"(p));
    return a;
}

__device__ __forceinline__ void mma_bf16(float* c, uint32_t a0, uint32_t a1,
                                         uint32_t a2, uint32_t a3,
                                         uint32_t b0, uint32_t b1) {
    asm volatile(
        "mma.sync.aligned.m16n8k16.row.col.f32.bf16.bf16.f32 "
        "{%0,%1,%2,%3}, {%4,%5,%6,%7}, {%8,%9}, {%0,%1,%2,%3};"
        : "+f"(c[0]), "+f"(c[1]), "+f"(c[2]), "+f"(c[3])
        : "r"(a0), "r"(a1), "r"(a2), "r"(a3), "r"(b0), "r"(b1));
}

__device__ __forceinline__ void ldmx4(uint32_t& r0, uint32_t& r1,
                                      uint32_t& r2, uint32_t& r3, uint32_t addr) {
    asm volatile("ldmatrix.sync.aligned.m8n8.x4.shared.b16 {%0,%1,%2,%3}, [%4];"
                 : "=r"(r0), "=r"(r1), "=r"(r2), "=r"(r3) : "r"(addr));
}

__device__ __forceinline__ uint32_t pack_split(float f) {
    __nv_bfloat16 h = __float2bfloat16(f);
    __nv_bfloat16 l = __float2bfloat16(f - __bfloat162float(h));
    return (uint32_t)__bfloat16_as_ushort(h) | ((uint32_t)__bfloat16_as_ushort(l) << 16);
}

// ---------------- fused prep: all 7 weights in one launch ----------------
struct WSpec { const float* w; int off; int K; int M; int start; };

__global__ void pack_all_weights_kernel(WSpec s0, WSpec s1, WSpec s2, WSpec s3,
                                        WSpec s4, WSpec s5, WSpec s6, int total)
{
    int idx = blockIdx.x * blockDim.x + threadIdx.x;
    if (idx >= total) return;
    WSpec s;
    if      (idx < s1.start) s = s0;
    else if (idx < s2.start) s = s1;
    else if (idx < s3.start) s = s2;
    else if (idx < s4.start) s = s3;
    else if (idx < s5.start) s = s4;
    else if (idx < s6.start) s = s5;
    else                     s = s6;
    int li = idx - s.start;
    int k = li / s.M, m = li % s.M;
    float v = s.w[li];
    __nv_bfloat16 h = __float2bfloat16(v);
    __nv_bfloat16 l = __float2bfloat16(v - __bfloat162float(h));
    g_whi[s.off + (size_t)m * s.K + k] = h;
    g_wlo[s.off + (size_t)m * s.K + k] = l;
}

// ---------------- zero counts (both graphs) + out ----------------
__global__ void zero_kernel(int* counts, int* counts2, float* outv, int N)
{
    int t = blockIdx.x * blockDim.x + threadIdx.x;
    int stride = gridDim.x * blockDim.x;
    for (int x = t; x < N; x += stride) { counts[x] = 0; counts2[x] = 0; outv[x] = 0.0f; }
}

// ---------------- CSR build (both graphs fused) ----------------
__global__ void hist_both_kernel(const int* __restrict__ idx1, int E1,
                                 const int* __restrict__ idx2, int E2,
                                 int* __restrict__ c1, int* __restrict__ c2)
{
    int t = blockIdx.x * blockDim.x + threadIdx.x;
    if (t < E1) atomicAdd(&c1[idx1[t]], 1);
    else if (t < E1 + E2) atomicAdd(&c2[idx2[t - E1]], 1);
}

// blockIdx < nb -> graph1, else graph2
__global__ void scanA_both_kernel(const int* __restrict__ c1, int* __restrict__ o1,
                                  int* __restrict__ p1,
                                  const int* __restrict__ c2, int* __restrict__ o2,
                                  int* __restrict__ p2, int N, int nb)
{
    __shared__ int s[1024];
    const int* counts; int* offsets; int* partial; int blk;
    if ((int)blockIdx.x < nb) { counts = c1; offsets = o1; partial = p1; blk = blockIdx.x; }
    else                      { counts = c2; offsets = o2; partial = p2; blk = blockIdx.x - nb; }
    int t = threadIdx.x;
    int i = blk * 1024 + t;
    int v = (i < N) ? counts[i] : 0;
    s[t] = v;
    __syncthreads();
#pragma unroll
    for (int o = 1; o < 1024; o <<= 1) {
        int x = (t >= o) ? s[t - o] : 0;
        __syncthreads();
        s[t] += x;
        __syncthreads();
    }
    if (i < N) offsets[i] = s[t] - v;
    if (t == 1023) partial[blk] = s[1023];
}

__global__ void scanB_both_kernel(int* __restrict__ p1, int* __restrict__ p2, int nb)
{
    if (threadIdx.x == 0 && blockIdx.x == 0) {
        int run = 0;
        for (int i = 0; i < nb; i++) { int t = p1[i]; p1[i] = run; run += t; }
        run = 0;
        for (int i = 0; i < nb; i++) { int t = p2[i]; p2[i] = run; run += t; }
    }
}

__global__ void scanC_both_kernel(int* __restrict__ o1, const int* __restrict__ p1,
                                  int* __restrict__ r1,
                                  int* __restrict__ o2, const int* __restrict__ p2,
                                  int* __restrict__ r2, int N)
{
    int i = blockIdx.x * blockDim.x + threadIdx.x;
    if (i < N) {
        int o = o1[i] + p1[i >> 10];
        o1[i] = o; r1[i] = o;
    } else if (i < 2 * N) {
        int j = i - N;
        int o = o2[j] + p2[j >> 10];
        o2[j] = o; r2[j] = o;
    }
}

__global__ void fill_both_kernel(const int* __restrict__ idx1, int E1,
                                 int* __restrict__ r1, int* __restrict__ eorder,
                                 const int* __restrict__ idx2, int E2,
                                 int* __restrict__ r2, int* __restrict__ pos)
{
    int t = blockIdx.x * blockDim.x + threadIdx.x;
    if (t < E1) {
        int slot = atomicAdd(&r1[idx1[t]], 1);
        eorder[slot] = t;
    } else if (t < E1 + E2) {
        int e = t - E1;
        int slot = atomicAdd(&r2[idx2[e]], 1);
        pos[e] = slot;
    }
}

// warp per node: sequential sum of its edges' rows; writes packed v directly
__global__ void csr_sum_kernel(const float4* __restrict__ e2,
                               const int* __restrict__ eorder,
                               const int* __restrict__ offsets,
                               const int* __restrict__ counts,
                               uint32_t* __restrict__ vp, int N)
{
    int gwarp = (blockIdx.x * blockDim.x + threadIdx.x) >> 5;
    int lane = threadIdx.x & 31;
    if (gwarp >= N) return;
    int beg = offsets[gwarp];
    int end = beg + counts[gwarp];
    float4 acc = make_float4(0.f, 0.f, 0.f, 0.f);
    for (int k = beg; k < end; k++) {
        int row = eorder[k];
        float4 v = e2[(size_t)row * 32 + lane];
        acc.x += v.x; acc.y += v.y; acc.z += v.z; acc.w += v.w;
    }
    uint4 o;
    o.x = pack_split(acc.x); o.y = pack_split(acc.y);
    o.z = pack_split(acc.z); o.w = pack_split(acc.w);
    *(uint4*)&vp[(size_t)gwarp * 128 + lane * 4] = o;
}

// warp per node: sum CONTIGUOUS ehull rows [off, off+cnt); write packed ohp
__global__ void hull_reduce_kernel(const float4* __restrict__ ehull,
                                   const int* __restrict__ offsets,
                                   const int* __restrict__ counts,
                                   uint32_t* __restrict__ ohp, int N)
{
    int gwarp = (blockIdx.x * blockDim.x + threadIdx.x) >> 5;
    int lane = threadIdx.x & 31;
    if (gwarp >= N) return;
    int beg = offsets[gwarp];
    int end = beg + counts[gwarp];
    float4 acc = make_float4(0.f, 0.f, 0.f, 0.f);
    for (int r = beg; r < end; r++) {
        float4 v = ehull[(size_t)r * 32 + lane];
        acc.x += v.x; acc.y += v.y; acc.z += v.z; acc.w += v.w;
    }
    uint4 o;
    o.x = pack_split(acc.x); o.y = pack_split(acc.y);
    o.z = pack_split(acc.z); o.w = pack_split(acc.w);
    *(uint4*)&ohp[(size_t)gwarp * 128 + lane * 4] = o;
}

// ---------------- warp-MMA bf16 split-3 GEMM (R10 proven core) ----------------
__global__ __launch_bounds__(256, 2) void gemm_mma(
    const uint32_t* __restrict__ A0, int lda0, int ksplit,
    const uint32_t* __restrict__ A1, int lda1,
    const __nv_bfloat16* __restrict__ WhiT, const __nv_bfloat16* __restrict__ WloT,
    int ldw, const float* __restrict__ bias,
    void* __restrict__ Cout, int outPacked,
    const float* __restrict__ wout, float* __restrict__ outv,
    int Nrows, int K, int M, int act)
{
    __shared__ __nv_bfloat16 sAhi[128 * SAS];
    __shared__ __nv_bfloat16 sAlo[128 * SAS];
    __shared__ __nv_bfloat16 sBhi[128 * SBS];
    __shared__ __nv_bfloat16 sBlo[128 * SBS];

    int tid = threadIdx.x;
    int wid = tid >> 5;
    int lane = tid & 31;
    int warpRow = wid & 3;
    int warpCol = wid >> 2;
    int row0 = blockIdx.x * 128;
    int col0 = blockIdx.y * 128;

    float c[2][8][4];
#pragma unroll
    for (int mf = 0; mf < 2; mf++)
#pragma unroll
        for (int nf = 0; nf < 8; nf++)
#pragma unroll
            for (int q = 0; q < 4; q++) c[mf][nf][q] = 0.0f;

    int qrow = lane >> 2;
    int qcol = lane & 3;

    for (int k0 = 0; k0 < K; k0 += KBLK) {
        const uint32_t* srcA;
        int kbase, ld;
        if (k0 < ksplit) { srcA = A0; kbase = k0; ld = lda0; }
        else             { srcA = A1; kbase = k0 - ksplit; ld = lda1; }
#pragma unroll
        for (int it = 0; it < 4; it++) {
            int idx = tid + it * 256;
            int r = idx >> 3;
            int kq = (idx & 7) * 4;
            uint4 u = make_uint4(0u, 0u, 0u, 0u);
            int grow = row0 + r;
            if (grow < Nrows)
                u = *(const uint4*)&srcA[(size_t)grow * ld + kbase + kq];
            uint32_t hi01 = __byte_perm(u.x, u.y, 0x5410);
            uint32_t lo01 = __byte_perm(u.x, u.y, 0x7632);
            uint32_t hi23 = __byte_perm(u.z, u.w, 0x5410);
            uint32_t lo23 = __byte_perm(u.z, u.w, 0x7632);
            int base = r * SAS + kq;
            *(uint2*)&sAhi[base] = make_uint2(hi01, hi23);
            *(uint2*)&sAlo[base] = make_uint2(lo01, lo23);
        }
#pragma unroll
        for (int it = 0; it < 4; it++) {
            int idx = tid + it * 256;
            int n = idx >> 3;
            int kq = (idx & 7) * 4;
            size_t goff = (size_t)(col0 + n) * ldw + k0 + kq;
            uint2 uh = *(const uint2*)&WhiT[goff];
            uint2 ul = *(const uint2*)&WloT[goff];
            int b = n * SBS + kq;
            *(uint32_t*)&sBhi[b]     = uh.x;
            *(uint32_t*)&sBhi[b + 2] = uh.y;
            *(uint32_t*)&sBlo[b]     = ul.x;
            *(uint32_t*)&sBlo[b + 2] = ul.y;
        }
        __syncthreads();

#pragma unroll
        for (int kc = 0; kc < KBLK; kc += 16) {
            uint32_t ah[2][4], al[2][4];
#pragma unroll
            for (int mf = 0; mf < 2; mf++) {
                int r = warpRow * 32 + mf * 16 + qrow;
                int i0 = r * SAS + kc + 2 * qcol;
                ah[mf][0] = *(const uint32_t*)&sAhi[i0];
                ah[mf][1] = *(const uint32_t*)&sAhi[i0 + 8 * SAS];
                ah[mf][2] = *(const uint32_t*)&sAhi[i0 + 8];
                ah[mf][3] = *(const uint32_t*)&sAhi[i0 + 8 * SAS + 8];
                al[mf][0] = *(const uint32_t*)&sAlo[i0];
                al[mf][1] = *(const uint32_t*)&sAlo[i0 + 8 * SAS];
                al[mf][2] = *(const uint32_t*)&sAlo[i0 + 8];
                al[mf][3] = *(const uint32_t*)&sAlo[i0 + 8 * SAS + 8];
            }
#pragma unroll
            for (int nf = 0; nf < 8; nf++) {
                int n = warpCol * 64 + nf * 8 + qrow;
                int i0 = n * SBS + kc + 2 * qcol;
                uint32_t bh0 = *(const uint32_t*)&sBhi[i0];
                uint32_t bh1 = *(const uint32_t*)&sBhi[i0 + 8];
                uint32_t bl0 = *(const uint32_t*)&sBlo[i0];
                uint32_t bl1 = *(const uint32_t*)&sBlo[i0 + 8];
#pragma unroll
                for (int mf = 0; mf < 2; mf++) {
                    mma_bf16(c[mf][nf], ah[mf][0], ah[mf][1], ah[mf][2], ah[mf][3], bh0, bh1);
                    mma_bf16(c[mf][nf], ah[mf][0], ah[mf][1], ah[mf][2], ah[mf][3], bl0, bl1);
                    mma_bf16(c[mf][nf], al[mf][0], al[mf][1], al[mf][2], al[mf][3], bh0, bh1);
                }
            }
        }
        __syncthreads();
    }

#pragma unroll
    for (int mf = 0; mf < 2; mf++) {
        int rbase = row0 + warpRow * 32 + mf * 16 + qrow;
        float sumA = 0.0f, sumB = 0.0f;
#pragma unroll
        for (int nf = 0; nf < 8; nf++) {
            int colp = col0 + warpCol * 64 + nf * 8 + 2 * qcol;
            float b0v = 0.f, b1v = 0.f;
            if (bias) { b0v = bias[colp]; b1v = bias[colp + 1]; }
            float f0 = c[mf][nf][0] + b0v;
            float f1 = c[mf][nf][1] + b1v;
            float f2 = c[mf][nf][2] + b0v;
            float f3 = c[mf][nf][3] + b1v;
            if (act) { f0 = silu_f(f0); f1 = silu_f(f1); f2 = silu_f(f2); f3 = silu_f(f3); }
            if (wout) {
                float w0v = __ldg(&wout[colp]);
                float w1v = __ldg(&wout[colp + 1]);
                sumA += f0 * w0v + f1 * w1v;
                sumB += f2 * w0v + f3 * w1v;
            } else if (outPacked) {
                uint32_t* Cp = (uint32_t*)Cout;
                if (rbase < Nrows)
                    *(uint2*)&Cp[(size_t)rbase * M + colp] =
                        make_uint2(pack_split(f0), pack_split(f1));
                if (rbase + 8 < Nrows)
                    *(uint2*)&Cp[(size_t)(rbase + 8) * M + colp] =
                        make_uint2(pack_split(f2), pack_split(f3));
            } else {
                float* Cf = (float*)Cout;
                if (rbase < Nrows)
                    *(float2*)&Cf[(size_t)rbase * M + colp] = make_float2(f0, f1);
                if (rbase + 8 < Nrows)
                    *(float2*)&Cf[(size_t)(rbase + 8) * M + colp] = make_float2(f2, f3);
            }
        }
        if (wout) {
            if (rbase < Nrows)     atomicAdd(&outv[rbase], sumA);
            if (rbase + 8 < Nrows) atomicAdd(&outv[rbase + 8], sumB);
        }
    }
}

// ---------------- hull kernel: MLP + MMA + gather, STG to CSR slots ----------
#define HULL_SMEM_BYTES ((2 * 128 * HSBS + 2 * HTILE * HSAS) * 2 + (HTILE * 16 + 128) * 4)

__global__ __launch_bounds__(256, 2) void hull_kernel(
    const float* __restrict__ fea,
    const int* __restrict__ jidx, const int* __restrict__ pos,
    const float* __restrict__ w0, const float* __restrict__ b0,
    const float* __restrict__ w1, const float* __restrict__ b1,
    const float* __restrict__ vhull, float* __restrict__ ehull, int EHn)
{
    extern __shared__ char smraw[];
    __nv_bfloat16* s_w1hi  = (__nv_bfloat16*)smraw;
    __nv_bfloat16* s_w1lo  = s_w1hi + 128 * HSBS;
    __nv_bfloat16* s_hidhi = s_w1lo + 128 * HSBS;
    __nv_bfloat16* s_hidlo = s_hidhi + HTILE * HSAS;
    float* s_fea = (float*)(s_hidlo + HTILE * HSAS);
    float* s_b1  = s_fea + HTILE * 16;

    int tid = threadIdx.x;
    int wid = tid >> 5;
    int lane = tid & 31;
    int warpRow = wid & 1;
    int warpCol = wid >> 1;
    int qrow = lane >> 2;
    int qcol = lane & 3;
    int col = tid & 127;
    int wg  = tid >> 7;
    int g  = lane >> 3;
    int lr = lane & 7;

    for (int t = tid; t < 16384; t += 256) {
        int k = t >> 7, n = t & 127;
        float v = w1[t];
        __nv_bfloat16 h = __float2bfloat16(v);
        __nv_bfloat16 l = __float2bfloat16(v - __bfloat162float(h));
        s_w1hi[n * HSBS + k] = h;
        s_w1lo[n * HSBS + k] = l;
    }
    if (tid < 128) s_b1[tid] = b1[tid];
    float rw0[16];
#pragma unroll
    for (int k = 0; k < 16; k++) rw0[k] = w0[k * 128 + col];
    float rb0 = b0[col];

    uint32_t bHhi = smem_u32(s_hidhi), bHlo = smem_u32(s_hidlo);
    uint32_t bWhi = smem_u32(s_w1hi),  bWlo = smem_u32(s_w1lo);
    uint32_t aRowPart = (uint32_t)((warpRow * 16 + (g & 1) * 8 + lr) * HSAS * 2
                                   + (g >> 1) * 16);
    uint32_t bRowPart[2];
#pragma unroll
    for (int p = 0; p < 2; p++)
        bRowPart[p] = (uint32_t)(((warpCol * 32 + (2 * p + (g >> 1)) * 8 + lr) * HSBS
                                  + (g & 1) * 8) * 2);
    __syncthreads();

    for (int base = blockIdx.x * HTILE; base < EHn; base += gridDim.x * HTILE) {
        int ec = min(HTILE, EHn - base);

        for (int t = tid; t < ec * 16; t += 256)
            s_fea[t] = fea[(size_t)base * 16 + t];
        __syncthreads();

        int e0 = wg * 16, e1 = min(ec, e0 + 16);
        for (int e = e0; e < e1; e++) {
            float acc = rb0;
#pragma unroll
            for (int k = 0; k < 16; k++)
                acc += s_fea[e * 16 + k] * rw0[k];
            float hv = silu_f(acc);
            __nv_bfloat16 h = __float2bfloat16(hv);
            __nv_bfloat16 l = __float2bfloat16(hv - __bfloat162float(h));
            s_hidhi[e * HSAS + col] = h;
            s_hidlo[e * HSAS + col] = l;
        }
        __syncthreads();

        float c[4][4];
#pragma unroll
        for (int nf = 0; nf < 4; nf++)
#pragma unroll
            for (int q = 0; q < 4; q++) c[nf][q] = 0.0f;

#pragma unroll
        for (int kc = 0; kc < 128; kc += 16) {
            uint32_t kOff = kc * 2;
            uint32_t ah0, ah1, ah2, ah3, al0, al1, al2, al3;
            ldmx4(ah0, ah1, ah2, ah3, bHhi + aRowPart + kOff);
            ldmx4(al0, al1, al2, al3, bHlo + aRowPart + kOff);
#pragma unroll
            for (int p = 0; p < 2; p++) {
                uint32_t bh0, bh1, bh2, bh3, bl0, bl1, bl2, bl3;
                ldmx4(bh0, bh1, bh2, bh3, bWhi + bRowPart[p] + kOff);
                ldmx4(bl0, bl1, bl2, bl3, bWlo + bRowPart[p] + kOff);
                mma_bf16(c[2*p],   ah0, ah1, ah2, ah3, bh0, bh1);
                mma_bf16(c[2*p],   ah0, ah1, ah2, ah3, bl0, bl1);
                mma_bf16(c[2*p],   al0, al1, al2, al3, bh0, bh1);
                mma_bf16(c[2*p+1], ah0, ah1, ah2, ah3, bh2, bh3);
                mma_bf16(c[2*p+1], ah0, ah1, ah2, ah3, bl2, bl3);
                mma_bf16(c[2*p+1], al0, al1, al2, al3, bh2, bh3);
            }
        }

        // epilogue: gather-multiply, STG to CSR slot rows (no atomics)
        int eA = warpRow * 16 + qrow;
        int eB = eA + 8;
        int jA = 0, sA = 0, jB = 0, sB = 0;
        bool vA = eA < ec, vB = eB < ec;
        if (vA) { jA = jidx[base + eA]; sA = pos[base + eA]; }
        if (vB) { jB = jidx[base + eB]; sB = pos[base + eB]; }
#pragma unroll
        for (int nf = 0; nf < 4; nf++) {
            int cp = warpCol * 32 + nf * 8 + 2 * qcol;
            float bb0 = s_b1[cp], bb1 = s_b1[cp + 1];
            if (vA) {
                float2 vh = *(const float2*)&vhull[(size_t)jA * 128 + cp];
                *(float2*)&ehull[(size_t)sA * 128 + cp] =
                    make_float2((c[nf][0] + bb0) * vh.x, (c[nf][1] + bb1) * vh.y);
            }
            if (vB) {
                float2 vh = *(const float2*)&vhull[(size_t)jB * 128 + cp];
                *(float2*)&ehull[(size_t)sB * 128 + cp] =
                    make_float2((c[nf][2] + bb0) * vh.x, (c[nf][3] + bb1) * vh.y);
            }
        }
        __syncthreads();
    }
}

// ---------------- launch ----------------
static void launch_gemm(const uint32_t* A0, int lda0, int ksplit,
                        const uint32_t* A1, int lda1,
                        const __nv_bfloat16* whiT, const __nv_bfloat16* wloT, int ldw,
                        const float* bias, void* C, int outPacked,
                        const float* wout, float* outv,
                        int N, int K, int M, int act)
{
    dim3 grid((N + 127) / 128, M / 128);
    gemm_mma<<<grid, 256>>>(A0, lda0, ksplit, A1, lda1, whiT, wloT, ldw,
                            bias, C, outPacked, wout, outv, N, K, M, act);
}

extern "C" void kernel_launch(void* const* d_in, const int* in_sizes, int n_in,
                              void* d_out, int out_size)
{
    const float* e2    = (const float*)d_in[0];
    const int*   iedge = (const int*)  d_in[1];
    const float* fea   = (const float*)d_in[2];
    const int*   eih   = (const int*)  d_in[3];
    const float* w_hull= (const float*)d_in[4];
    const float* w0    = (const float*)d_in[5];
    const float* b0    = (const float*)d_in[6];
    const float* w1    = (const float*)d_in[7];
    const float* b1    = (const float*)d_in[8];
    const float* w1h   = (const float*)d_in[9];
    const float* b1h   = (const float*)d_in[10];
    const float* w2h   = (const float*)d_in[11];
    const float* b2h   = (const float*)d_in[12];
    const float* wcat  = (const float*)d_in[13];
    const float* bcat  = (const float*)d_in[14];
    const float* wup   = (const float*)d_in[15];
    const float* bup   = (const float*)d_in[16];
    const float* wl0   = (const float*)d_in[17];
    const float* bl0   = (const float*)d_in[18];
    const float* wl1   = (const float*)d_in[19];
    const float* bl1   = (const float*)d_in[20];
    const float* wout  = (const float*)d_in[21];
    float* out = (float*)d_out;

    int N  = out_size;
    int E  = in_sizes[1];
    int EH = in_sizes[2] / 16;
    const int* jh = eih;
    const int* ih = eih + EH;

    float *pvh, *peh;
    uint32_t *pvp, *pohp, *pt128p, *pa256p, *pb256p;
    __nv_bfloat16 *pwhi, *pwlo;
    int *pcnt, *poff, *prun, *ppart, *peord;
    int *pcnt2, *poff2, *prun2, *ppart2, *ppos;
    cudaGetSymbolAddress((void**)&pvh,    g_vhull);
    cudaGetSymbolAddress((void**)&peh,    g_ehull);
    cudaGetSymbolAddress((void**)&pvp,    g_vp);
    cudaGetSymbolAddress((void**)&pohp,   g_ohp);
    cudaGetSymbolAddress((void**)&pt128p, g_t128p);
    cudaGetSymbolAddress((void**)&pa256p, g_a256p);
    cudaGetSymbolAddress((void**)&pb256p, g_b256p);
    cudaGetSymbolAddress((void**)&pwhi,   g_whi);
    cudaGetSymbolAddress((void**)&pwlo,   g_wlo);
    cudaGetSymbolAddress((void**)&pcnt,   g_counts);
    cudaGetSymbolAddress((void**)&poff,   g_offsets);
    cudaGetSymbolAddress((void**)&prun,   g_running);
    cudaGetSymbolAddress((void**)&ppart,  g_partial);
    cudaGetSymbolAddress((void**)&peord,  g_eorder);
    cudaGetSymbolAddress((void**)&pcnt2,  g_counts2);
    cudaGetSymbolAddress((void**)&poff2,  g_offsets2);
    cudaGetSymbolAddress((void**)&prun2,  g_running2);
    cudaGetSymbolAddress((void**)&ppart2, g_partial2);
    cudaGetSymbolAddress((void**)&ppos,   g_pos);

    cudaFuncSetAttribute(hull_kernel, cudaFuncAttributeMaxDynamicSharedMemorySize,
                         HULL_SMEM_BYTES);
    cudaFuncSetAttribute(hull_kernel, cudaFuncAttributePreferredSharedMemoryCarveout,
                         100);

    // 0. pre-split ALL weights in one launch
    {
        WSpec s0 = { w_hull, OFF_WHULL, 128, 128, 0 };
        WSpec s1 = { w1h,    OFF_W1H,   128, 128, 16384 };
        WSpec s2 = { w2h,    OFF_W2H,   128, 256, 32768 };
        WSpec s3 = { wcat,   OFF_WCAT,  384, 128, 65536 };
        WSpec s4 = { wup,    OFF_WUP,   128, 256, 114688 };
        WSpec s5 = { wl0,    OFF_WL0,   256, 256, 147456 };
        WSpec s6 = { wl1,    OFF_WL1,   256, 256, 212992 };
        pack_all_weights_kernel<<<(WPLANE_TOTAL + 255) / 256, 256>>>(
            s0, s1, s2, s3, s4, s5, s6, WPLANE_TOTAL);
    }

    // 1. zero counts (both) + out
    zero_kernel<<<512, 256>>>(pcnt, pcnt2, out, N);

    // 2. fused CSR build for BOTH graphs
    int nb = (N + 1023) / 1024;
    hist_both_kernel<<<(E + EH + 255) / 256, 256>>>(iedge, E, ih, EH, pcnt, pcnt2);
    scanA_both_kernel<<<2 * nb, 1024>>>(pcnt, poff, ppart, pcnt2, poff2, ppart2, N, nb);
    scanB_both_kernel<<<1, 32>>>(ppart, ppart2, nb);
    scanC_both_kernel<<<(2 * N + 255) / 256, 256>>>(poff, ppart, prun,
                                                    poff2, ppart2, prun2, N);
    fill_both_kernel<<<(E + EH + 255) / 256, 256>>>(iedge, E, prun, peord,
                                                    ih, EH, prun2, ppos);
    csr_sum_kernel<<<(N * 32 + 255) / 256, 256>>>(
        (const float4*)e2, peord, poff, pcnt, pvp, N);

    // 3. v_hull = v @ w_hull (fp32 out for hull gather)
    launch_gemm(pvp, 128, 128, pvp, 128, pwhi + OFF_WHULL, pwlo + OFF_WHULL, 128,
                nullptr, pvh, 0, nullptr, nullptr, N, 128, 128, 0);

    // 4. hull message passing (STG to slots) + reduce -> packed ohp
    hull_kernel<<<296, 256, HULL_SMEM_BYTES>>>(
        fea, jh, ppos, w0, b0, w1, b1, pvh, peh, EH);
    hull_reduce_kernel<<<(N * 32 + 255) / 256, 256>>>(
        (const float4*)peh, poff2, pcnt2, pohp, N);

    // 5. t128p = silu(oh @ w1_hull + b1_hull)
    launch_gemm(pohp, 128, 128, pohp, 128, pwhi + OFF_W1H, pwlo + OFF_W1H, 128,
                b1h, pt128p, 1, nullptr, nullptr, N, 128, 128, 1);
    // 6. a256p = t128 @ w2_hull + b2_hull
    launch_gemm(pt128p, 128, 128, pt128p, 128, pwhi + OFF_W2H, pwlo + OFF_W2H, 128,
                b2h, pa256p, 1, nullptr, nullptr, N, 128, 256, 0);
    // 7. t128p = silu([v | a256] @ w_cat + b_cat)   (K = 384)
    launch_gemm(pvp, 128, 128, pa256p, 256, pwhi + OFF_WCAT, pwlo + OFF_WCAT, 384,
                bcat, pt128p, 1, nullptr, nullptr, N, 384, 128, 1);
    // 8. b256p = t128 @ w_up + b_up
    launch_gemm(pt128p, 128, 128, pt128p, 128, pwhi + OFF_WUP, pwlo + OFF_WUP, 128,
                bup, pb256p, 1, nullptr, nullptr, N, 128, 256, 0);
    // 9. a256p = silu(b256 @ w_l0 + b_l0)
    launch_gemm(pb256p, 256, 256, pb256p, 256, pwhi + OFF_WL0, pwlo + OFF_WL0, 256,
                bl0, pa256p, 1, nullptr, nullptr, N, 256, 256, 1);
    // 10+11 fused: out += silu(a256 @ w_l1 + b_l1) . w_out
    launch_gemm(pa256p, 256, 256, pa256p, 256, pwhi + OFF_WL1, pwlo + OFF_WL1, 256,
                bl1, nullptr, 0, wout, out, N, 256, 256, 1);
}

// round 16
// speedup vs baseline: 1.2512x; 1.0489x over previous
#include <cuda_runtime.h>
#include <cuda_bf16.h>
#include <math.h>
#include <stdint.h>

#define NMAX 100000
#define EMAX 1000000
#define EHMAX 500000
#define KBLK 32
#define HTILE 32
#define SAS 40
#define SBS 42
#define TAS 136      // stage-2 resident A tile stride (conflict-free)
#define HSAS 136
#define HSBS 136

// weight-plane offsets (bf16 elements, transposed [M][K])
#define OFF_WHULL 0
#define OFF_W1H   16384
#define OFF_W2H   32768
#define OFF_WCAT  65536
#define OFF_WUP   114688
#define OFF_WL0   147456
#define OFF_WL1   212992
#define WPLANE_TOTAL 278528

#define GEMM2_SMEM_BYTES ((2 * 128 * TAS + 2 * 128 * SBS) * 2)

// ---------------- scratch ----------------
__device__ float    g_vhull[(size_t)NMAX * 128];
__device__ float    g_ehull[(size_t)EHMAX * 128];
__device__ uint32_t g_vp   [(size_t)NMAX * 128];
__device__ uint32_t g_ohp  [(size_t)NMAX * 128];
__device__ uint32_t g_a256p[(size_t)NMAX * 256];
__device__ uint32_t g_b256p[(size_t)NMAX * 256];
__device__ __nv_bfloat16 g_whi[WPLANE_TOTAL];
__device__ __nv_bfloat16 g_wlo[WPLANE_TOTAL];
// CSR scratch (main graph)
__device__ int g_counts [NMAX];
__device__ int g_offsets[NMAX];
__device__ int g_running[NMAX];
__device__ int g_partial[128];
__device__ int g_eorder [EMAX];
// CSR scratch (hull graph)
__device__ int g_counts2 [NMAX];
__device__ int g_offsets2[NMAX];
__device__ int g_running2[NMAX];
__device__ int g_partial2[128];
__device__ int g_pos     [EHMAX];

__device__ __forceinline__ float silu_f(float x) { return x / (1.0f + expf(-x)); }

__device__ __forceinline__ uint32_t smem_u32(const void* p) {
    uint32_t a;
    asm("{ .reg .u64 t; cvta.to.shared.u64 t, %1; cvt.u32.u64 %0, t; }" : "=r"(a) : "l"(p));
    return a;
}

__device__ __forceinline__ void mma_bf16(float* c, uint32_t a0, uint32_t a1,
                                         uint32_t a2, uint32_t a3,
                                         uint32_t b0, uint32_t b1) {
    asm volatile(
        "mma.sync.aligned.m16n8k16.row.col.f32.bf16.bf16.f32 "
        "{%0,%1,%2,%3}, {%4,%5,%6,%7}, {%8,%9}, {%0,%1,%2,%3};"
        : "+f"(c[0]), "+f"(c[1]), "+f"(c[2]), "+f"(c[3])
        : "r"(a0), "r"(a1), "r"(a2), "r"(a3), "r"(b0), "r"(b1));
}

__device__ __forceinline__ void ldmx4(uint32_t& r0, uint32_t& r1,
                                      uint32_t& r2, uint32_t& r3, uint32_t addr) {
    asm volatile("ldmatrix.sync.aligned.m8n8.x4.shared.b16 {%0,%1,%2,%3}, [%4];"
                 : "=r"(r0), "=r"(r1), "=r"(r2), "=r"(r3) : "r"(addr));
}

__device__ __forceinline__ uint32_t pack_split(float f) {
    __nv_bfloat16 h = __float2bfloat16(f);
    __nv_bfloat16 l = __float2bfloat16(f - __bfloat162float(h));
    return (uint32_t)__bfloat16_as_ushort(h) | ((uint32_t)__bfloat16_as_ushort(l) << 16);
}

// ---------------- fused prep: all 7 weights in one launch ----------------
struct WSpec { const float* w; int off; int K; int M; int start; };

__global__ void pack_all_weights_kernel(WSpec s0, WSpec s1, WSpec s2, WSpec s3,
                                        WSpec s4, WSpec s5, WSpec s6, int total)
{
    int idx = blockIdx.x * blockDim.x + threadIdx.x;
    if (idx >= total) return;
    WSpec s;
    if      (idx < s1.start) s = s0;
    else if (idx < s2.start) s = s1;
    else if (idx < s3.start) s = s2;
    else if (idx < s4.start) s = s3;
    else if (idx < s5.start) s = s4;
    else if (idx < s6.start) s = s5;
    else                     s = s6;
    int li = idx - s.start;
    int k = li / s.M, m = li % s.M;
    float v = s.w[li];
    __nv_bfloat16 h = __float2bfloat16(v);
    __nv_bfloat16 l = __float2bfloat16(v - __bfloat162float(h));
    g_whi[s.off + (size_t)m * s.K + k] = h;
    g_wlo[s.off + (size_t)m * s.K + k] = l;
}

__global__ void zero_kernel(int* counts, int* counts2, float* outv, int N)
{
    int t = blockIdx.x * blockDim.x + threadIdx.x;
    int stride = gridDim.x * blockDim.x;
    for (int x = t; x < N; x += stride) { counts[x] = 0; counts2[x] = 0; outv[x] = 0.0f; }
}

// ---------------- CSR build (both graphs fused) ----------------
__global__ void hist_both_kernel(const int* __restrict__ idx1, int E1,
                                 const int* __restrict__ idx2, int E2,
                                 int* __restrict__ c1, int* __restrict__ c2)
{
    int t = blockIdx.x * blockDim.x + threadIdx.x;
    if (t < E1) atomicAdd(&c1[idx1[t]], 1);
    else if (t < E1 + E2) atomicAdd(&c2[idx2[t - E1]], 1);
}

__global__ void scanA_both_kernel(const int* __restrict__ c1, int* __restrict__ o1,
                                  int* __restrict__ p1,
                                  const int* __restrict__ c2, int* __restrict__ o2,
                                  int* __restrict__ p2, int N, int nb)
{
    __shared__ int s[1024];
    const int* counts; int* offsets; int* partial; int blk;
    if ((int)blockIdx.x < nb) { counts = c1; offsets = o1; partial = p1; blk = blockIdx.x; }
    else                      { counts = c2; offsets = o2; partial = p2; blk = blockIdx.x - nb; }
    int t = threadIdx.x;
    int i = blk * 1024 + t;
    int v = (i < N) ? counts[i] : 0;
    s[t] = v;
    __syncthreads();
#pragma unroll
    for (int o = 1; o < 1024; o <<= 1) {
        int x = (t >= o) ? s[t - o] : 0;
        __syncthreads();
        s[t] += x;
        __syncthreads();
    }
    if (i < N) offsets[i] = s[t] - v;
    if (t == 1023) partial[blk] = s[1023];
}

__global__ void scanB_both_kernel(int* __restrict__ p1, int* __restrict__ p2, int nb)
{
    if (threadIdx.x == 0 && blockIdx.x == 0) {
        int run = 0;
        for (int i = 0; i < nb; i++) { int t = p1[i]; p1[i] = run; run += t; }
        run = 0;
        for (int i = 0; i < nb; i++) { int t = p2[i]; p2[i] = run; run += t; }
    }
}

__global__ void scanC_both_kernel(int* __restrict__ o1, const int* __restrict__ p1,
                                  int* __restrict__ r1,
                                  int* __restrict__ o2, const int* __restrict__ p2,
                                  int* __restrict__ r2, int N)
{
    int i = blockIdx.x * blockDim.x + threadIdx.x;
    if (i < N) {
        int o = o1[i] + p1[i >> 10];
        o1[i] = o; r1[i] = o;
    } else if (i < 2 * N) {
        int j = i - N;
        int o = o2[j] + p2[j >> 10];
        o2[j] = o; r2[j] = o;
    }
}

__global__ void fill_both_kernel(const int* __restrict__ idx1, int E1,
                                 int* __restrict__ r1, int* __restrict__ eorder,
                                 const int* __restrict__ idx2, int E2,
                                 int* __restrict__ r2, int* __restrict__ pos)
{
    int t = blockIdx.x * blockDim.x + threadIdx.x;
    if (t < E1) {
        int slot = atomicAdd(&r1[idx1[t]], 1);
        eorder[slot] = t;
    } else if (t < E1 + E2) {
        int e = t - E1;
        int slot = atomicAdd(&r2[idx2[e]], 1);
        pos[e] = slot;
    }
}

__global__ void csr_sum_kernel(const float4* __restrict__ e2,
                               const int* __restrict__ eorder,
                               const int* __restrict__ offsets,
                               const int* __restrict__ counts,
                               uint32_t* __restrict__ vp, int N)
{
    int gwarp = (blockIdx.x * blockDim.x + threadIdx.x) >> 5;
    int lane = threadIdx.x & 31;
    if (gwarp >= N) return;
    int beg = offsets[gwarp];
    int end = beg + counts[gwarp];
    float4 acc = make_float4(0.f, 0.f, 0.f, 0.f);
    for (int k = beg; k < end; k++) {
        int row = eorder[k];
        float4 v = e2[(size_t)row * 32 + lane];
        acc.x += v.x; acc.y += v.y; acc.z += v.z; acc.w += v.w;
    }
    uint4 o;
    o.x = pack_split(acc.x); o.y = pack_split(acc.y);
    o.z = pack_split(acc.z); o.w = pack_split(acc.w);
    *(uint4*)&vp[(size_t)gwarp * 128 + lane * 4] = o;
}

__global__ void hull_reduce_kernel(const float4* __restrict__ ehull,
                                   const int* __restrict__ offsets,
                                   const int* __restrict__ counts,
                                   uint32_t* __restrict__ ohp, int N)
{
    int gwarp = (blockIdx.x * blockDim.x + threadIdx.x) >> 5;
    int lane = threadIdx.x & 31;
    if (gwarp >= N) return;
    int beg = offsets[gwarp];
    int end = beg + counts[gwarp];
    float4 acc = make_float4(0.f, 0.f, 0.f, 0.f);
    for (int r = beg; r < end; r++) {
        float4 v = ehull[(size_t)r * 32 + lane];
        acc.x += v.x; acc.y += v.y; acc.z += v.z; acc.w += v.w;
    }
    uint4 o;
    o.x = pack_split(acc.x); o.y = pack_split(acc.y);
    o.z = pack_split(acc.z); o.w = pack_split(acc.w);
    *(uint4*)&ohp[(size_t)gwarp * 128 + lane * 4] = o;
}

// ---------------- warp-MMA bf16 split-3 GEMM (R10 proven core) ----------------
__global__ __launch_bounds__(256, 2) void gemm_mma(
    const uint32_t* __restrict__ A0, int lda0, int ksplit,
    const uint32_t* __restrict__ A1, int lda1,
    const __nv_bfloat16* __restrict__ WhiT, const __nv_bfloat16* __restrict__ WloT,
    int ldw, const float* __restrict__ bias,
    void* __restrict__ Cout, int outPacked,
    const float* __restrict__ wout, float* __restrict__ outv,
    int Nrows, int K, int M, int act)
{
    __shared__ __nv_bfloat16 sAhi[128 * SAS];
    __shared__ __nv_bfloat16 sAlo[128 * SAS];
    __shared__ __nv_bfloat16 sBhi[128 * SBS];
    __shared__ __nv_bfloat16 sBlo[128 * SBS];

    int tid = threadIdx.x;
    int wid = tid >> 5;
    int lane = tid & 31;
    int warpRow = wid & 3;
    int warpCol = wid >> 2;
    int row0 = blockIdx.x * 128;
    int col0 = blockIdx.y * 128;

    float c[2][8][4];
#pragma unroll
    for (int mf = 0; mf < 2; mf++)
#pragma unroll
        for (int nf = 0; nf < 8; nf++)
#pragma unroll
            for (int q = 0; q < 4; q++) c[mf][nf][q] = 0.0f;

    int qrow = lane >> 2;
    int qcol = lane & 3;

    for (int k0 = 0; k0 < K; k0 += KBLK) {
        const uint32_t* srcA;
        int kbase, ld;
        if (k0 < ksplit) { srcA = A0; kbase = k0; ld = lda0; }
        else             { srcA = A1; kbase = k0 - ksplit; ld = lda1; }
#pragma unroll
        for (int it = 0; it < 4; it++) {
            int idx = tid + it * 256;
            int r = idx >> 3;
            int kq = (idx & 7) * 4;
            uint4 u = make_uint4(0u, 0u, 0u, 0u);
            int grow = row0 + r;
            if (grow < Nrows)
                u = *(const uint4*)&srcA[(size_t)grow * ld + kbase + kq];
            uint32_t hi01 = __byte_perm(u.x, u.y, 0x5410);
            uint32_t lo01 = __byte_perm(u.x, u.y, 0x7632);
            uint32_t hi23 = __byte_perm(u.z, u.w, 0x5410);
            uint32_t lo23 = __byte_perm(u.z, u.w, 0x7632);
            int base = r * SAS + kq;
            *(uint2*)&sAhi[base] = make_uint2(hi01, hi23);
            *(uint2*)&sAlo[base] = make_uint2(lo01, lo23);
        }
#pragma unroll
        for (int it = 0; it < 4; it++) {
            int idx = tid + it * 256;
            int n = idx >> 3;
            int kq = (idx & 7) * 4;
            size_t goff = (size_t)(col0 + n) * ldw + k0 + kq;
            uint2 uh = *(const uint2*)&WhiT[goff];
            uint2 ul = *(const uint2*)&WloT[goff];
            int b = n * SBS + kq;
            *(uint32_t*)&sBhi[b]     = uh.x;
            *(uint32_t*)&sBhi[b + 2] = uh.y;
            *(uint32_t*)&sBlo[b]     = ul.x;
            *(uint32_t*)&sBlo[b + 2] = ul.y;
        }
        __syncthreads();

#pragma unroll
        for (int kc = 0; kc < KBLK; kc += 16) {
            uint32_t ah[2][4], al[2][4];
#pragma unroll
            for (int mf = 0; mf < 2; mf++) {
                int r = warpRow * 32 + mf * 16 + qrow;
                int i0 = r * SAS + kc + 2 * qcol;
                ah[mf][0] = *(const uint32_t*)&sAhi[i0];
                ah[mf][1] = *(const uint32_t*)&sAhi[i0 + 8 * SAS];
                ah[mf][2] = *(const uint32_t*)&sAhi[i0 + 8];
                ah[mf][3] = *(const uint32_t*)&sAhi[i0 + 8 * SAS + 8];
                al[mf][0] = *(const uint32_t*)&sAlo[i0];
                al[mf][1] = *(const uint32_t*)&sAlo[i0 + 8 * SAS];
                al[mf][2] = *(const uint32_t*)&sAlo[i0 + 8];
                al[mf][3] = *(const uint32_t*)&sAlo[i0 + 8 * SAS + 8];
            }
#pragma unroll
            for (int nf = 0; nf < 8; nf++) {
                int n = warpCol * 64 + nf * 8 + qrow;
                int i0 = n * SBS + kc + 2 * qcol;
                uint32_t bh0 = *(const uint32_t*)&sBhi[i0];
                uint32_t bh1 = *(const uint32_t*)&sBhi[i0 + 8];
                uint32_t bl0 = *(const uint32_t*)&sBlo[i0];
                uint32_t bl1 = *(const uint32_t*)&sBlo[i0 + 8];
#pragma unroll
                for (int mf = 0; mf < 2; mf++) {
                    mma_bf16(c[mf][nf], ah[mf][0], ah[mf][1], ah[mf][2], ah[mf][3], bh0, bh1);
                    mma_bf16(c[mf][nf], ah[mf][0], ah[mf][1], ah[mf][2], ah[mf][3], bl0, bl1);
                    mma_bf16(c[mf][nf], al[mf][0], al[mf][1], al[mf][2], al[mf][3], bh0, bh1);
                }
            }
        }
        __syncthreads();
    }

#pragma unroll
    for (int mf = 0; mf < 2; mf++) {
        int rbase = row0 + warpRow * 32 + mf * 16 + qrow;
        float sumA = 0.0f, sumB = 0.0f;
#pragma unroll
        for (int nf = 0; nf < 8; nf++) {
            int colp = col0 + warpCol * 64 + nf * 8 + 2 * qcol;
            float b0v = 0.f, b1v = 0.f;
            if (bias) { b0v = bias[colp]; b1v = bias[colp + 1]; }
            float f0 = c[mf][nf][0] + b0v;
            float f1 = c[mf][nf][1] + b1v;
            float f2 = c[mf][nf][2] + b0v;
            float f3 = c[mf][nf][3] + b1v;
            if (act) { f0 = silu_f(f0); f1 = silu_f(f1); f2 = silu_f(f2); f3 = silu_f(f3); }
            if (wout) {
                float w0v = __ldg(&wout[colp]);
                float w1v = __ldg(&wout[colp + 1]);
                sumA += f0 * w0v + f1 * w1v;
                sumB += f2 * w0v + f3 * w1v;
            } else if (outPacked) {
                uint32_t* Cp = (uint32_t*)Cout;
                if (rbase < Nrows)
                    *(uint2*)&Cp[(size_t)rbase * M + colp] =
                        make_uint2(pack_split(f0), pack_split(f1));
                if (rbase + 8 < Nrows)
                    *(uint2*)&Cp[(size_t)(rbase + 8) * M + colp] =
                        make_uint2(pack_split(f2), pack_split(f3));
            } else {
                float* Cf = (float*)Cout;
                if (rbase < Nrows)
                    *(float2*)&Cf[(size_t)rbase * M + colp] = make_float2(f0, f1);
                if (rbase + 8 < Nrows)
                    *(float2*)&Cf[(size_t)(rbase + 8) * M + colp] = make_float2(f2, f3);
            }
        }
        if (wout) {
            if (rbase < Nrows)     atomicAdd(&outv[rbase], sumA);
            if (rbase + 8 < Nrows) atomicAdd(&outv[rbase + 8], sumB);
        }
    }
}

// ---------------- fused 2-layer GEMM ----------------
// Stage1: T[128rows x 128] = silu( [A0|A1] @ W1 + b1 )  (kept in SMEM hi/lo)
// Stage2: C2[128rows x 256] = T @ W2 + b2               (packed store)
__global__ __launch_bounds__(256, 2) void gemm2_mma(
    const uint32_t* __restrict__ A0, int lda0, int ksplit,
    const uint32_t* __restrict__ A1, int lda1,
    const __nv_bfloat16* __restrict__ W1hi, const __nv_bfloat16* __restrict__ W1lo,
    int ldw1, const float* __restrict__ bias1,
    const __nv_bfloat16* __restrict__ W2hi, const __nv_bfloat16* __restrict__ W2lo,
    const float* __restrict__ bias2,
    uint32_t* __restrict__ C2, int Nrows, int K1)
{
    extern __shared__ __nv_bfloat16 sm2[];
    __nv_bfloat16* sThi = sm2;                    // 128*TAS (stage1 A tiles alias front)
    __nv_bfloat16* sTlo = sThi + 128 * TAS;
    __nv_bfloat16* sBhi = sTlo + 128 * TAS;       // 128*SBS
    __nv_bfloat16* sBlo = sBhi + 128 * SBS;
    __nv_bfloat16* sAhi = sThi;                   // stage1 alias (stride SAS)
    __nv_bfloat16* sAlo = sTlo;

    int tid = threadIdx.x;
    int wid = tid >> 5;
    int lane = tid & 31;
    int warpRow = wid & 3;
    int warpCol = wid >> 2;
    int row0 = blockIdx.x * 128;
    int qrow = lane >> 2;
    int qcol = lane & 3;

    float c[2][8][4];
#pragma unroll
    for (int mf = 0; mf < 2; mf++)
#pragma unroll
        for (int nf = 0; nf < 8; nf++)
#pragma unroll
            for (int q = 0; q < 4; q++) c[mf][nf][q] = 0.0f;

    // ---------------- stage 1 ----------------
    for (int k0 = 0; k0 < K1; k0 += KBLK) {
        const uint32_t* srcA;
        int kbase, ld;
        if (k0 < ksplit) { srcA = A0; kbase = k0; ld = lda0; }
        else             { srcA = A1; kbase = k0 - ksplit; ld = lda1; }
#pragma unroll
        for (int it = 0; it < 4; it++) {
            int idx = tid + it * 256;
            int r = idx >> 3;
            int kq = (idx & 7) * 4;
            uint4 u = make_uint4(0u, 0u, 0u, 0u);
            int grow = row0 + r;
            if (grow < Nrows)
                u = *(const uint4*)&srcA[(size_t)grow * ld + kbase + kq];
            uint32_t hi01 = __byte_perm(u.x, u.y, 0x5410);
            uint32_t lo01 = __byte_perm(u.x, u.y, 0x7632);
            uint32_t hi23 = __byte_perm(u.z, u.w, 0x5410);
            uint32_t lo23 = __byte_perm(u.z, u.w, 0x7632);
            int base = r * SAS + kq;
            *(uint2*)&sAhi[base] = make_uint2(hi01, hi23);
            *(uint2*)&sAlo[base] = make_uint2(lo01, lo23);
        }
#pragma unroll
        for (int it = 0; it < 4; it++) {
            int idx = tid + it * 256;
            int n = idx >> 3;
            int kq = (idx & 7) * 4;
            size_t goff = (size_t)n * ldw1 + k0 + kq;
            uint2 uh = *(const uint2*)&W1hi[goff];
            uint2 ul = *(const uint2*)&W1lo[goff];
            int b = n * SBS + kq;
            *(uint32_t*)&sBhi[b]     = uh.x;
            *(uint32_t*)&sBhi[b + 2] = uh.y;
            *(uint32_t*)&sBlo[b]     = ul.x;
            *(uint32_t*)&sBlo[b + 2] = ul.y;
        }
        __syncthreads();

#pragma unroll
        for (int kc = 0; kc < KBLK; kc += 16) {
            uint32_t ah[2][4], al[2][4];
#pragma unroll
            for (int mf = 0; mf < 2; mf++) {
                int r = warpRow * 32 + mf * 16 + qrow;
                int i0 = r * SAS + kc + 2 * qcol;
                ah[mf][0] = *(const uint32_t*)&sAhi[i0];
                ah[mf][1] = *(const uint32_t*)&sAhi[i0 + 8 * SAS];
                ah[mf][2] = *(const uint32_t*)&sAhi[i0 + 8];
                ah[mf][3] = *(const uint32_t*)&sAhi[i0 + 8 * SAS + 8];
                al[mf][0] = *(const uint32_t*)&sAlo[i0];
                al[mf][1] = *(const uint32_t*)&sAlo[i0 + 8 * SAS];
                al[mf][2] = *(const uint32_t*)&sAlo[i0 + 8];
                al[mf][3] = *(const uint32_t*)&sAlo[i0 + 8 * SAS + 8];
            }
#pragma unroll
            for (int nf = 0; nf < 8; nf++) {
                int n = warpCol * 64 + nf * 8 + qrow;
                int i0 = n * SBS + kc + 2 * qcol;
                uint32_t bh0 = *(const uint32_t*)&sBhi[i0];
                uint32_t bh1 = *(const uint32_t*)&sBhi[i0 + 8];
                uint32_t bl0 = *(const uint32_t*)&sBlo[i0];
                uint32_t bl1 = *(const uint32_t*)&sBlo[i0 + 8];
#pragma unroll
                for (int mf = 0; mf < 2; mf++) {
                    mma_bf16(c[mf][nf], ah[mf][0], ah[mf][1], ah[mf][2], ah[mf][3], bh0, bh1);
                    mma_bf16(c[mf][nf], ah[mf][0], ah[mf][1], ah[mf][2], ah[mf][3], bl0, bl1);
                    mma_bf16(c[mf][nf], al[mf][0], al[mf][1], al[mf][2], al[mf][3], bh0, bh1);
                }
            }
        }
        __syncthreads();
    }

    // stage1 epilogue: bias + silu, split hi/lo into resident T tile (stride TAS)
#pragma unroll
    for (int mf = 0; mf < 2; mf++) {
        int r1 = warpRow * 32 + mf * 16 + qrow;
#pragma unroll
        for (int nf = 0; nf < 8; nf++) {
            int kp = warpCol * 64 + nf * 8 + 2 * qcol;   // stage2 K index
            float b0v = bias1[kp], b1v = bias1[kp + 1];
            float f0 = silu_f(c[mf][nf][0] + b0v);
            float f1 = silu_f(c[mf][nf][1] + b1v);
            float f2 = silu_f(c[mf][nf][2] + b0v);
            float f3 = silu_f(c[mf][nf][3] + b1v);
            __nv_bfloat16 h0 = __float2bfloat16(f0);
            __nv_bfloat16 h1 = __float2bfloat16(f1);
            __nv_bfloat16 h2 = __float2bfloat16(f2);
            __nv_bfloat16 h3 = __float2bfloat16(f3);
            __nv_bfloat16 l0 = __float2bfloat16(f0 - __bfloat162float(h0));
            __nv_bfloat16 l1 = __float2bfloat16(f1 - __bfloat162float(h1));
            __nv_bfloat16 l2 = __float2bfloat16(f2 - __bfloat162float(h2));
            __nv_bfloat16 l3 = __float2bfloat16(f3 - __bfloat162float(h3));
            *(uint32_t*)&sThi[r1 * TAS + kp] =
                (uint32_t)__bfloat16_as_ushort(h0) | ((uint32_t)__bfloat16_as_ushort(h1) << 16);
            *(uint32_t*)&sTlo[r1 * TAS + kp] =
                (uint32_t)__bfloat16_as_ushort(l0) | ((uint32_t)__bfloat16_as_ushort(l1) << 16);
            *(uint32_t*)&sThi[(r1 + 8) * TAS + kp] =
                (uint32_t)__bfloat16_as_ushort(h2) | ((uint32_t)__bfloat16_as_ushort(h3) << 16);
            *(uint32_t*)&sTlo[(r1 + 8) * TAS + kp] =
                (uint32_t)__bfloat16_as_ushort(l2) | ((uint32_t)__bfloat16_as_ushort(l3) << 16);
        }
    }

    // ---------------- stage 2: C2 = T @ W2 + b2, M=256, K=128 ----------------
    for (int half = 0; half < 2; half++) {
#pragma unroll
        for (int mf = 0; mf < 2; mf++)
#pragma unroll
            for (int nf = 0; nf < 8; nf++)
#pragma unroll
                for (int q = 0; q < 4; q++) c[mf][nf][q] = 0.0f;

        for (int kb = 0; kb < 4; kb++) {
            int k0 = kb * KBLK;
            __syncthreads();   // protect sB from previous compute / order sT writes
#pragma unroll
            for (int it = 0; it < 4; it++) {
                int idx = tid + it * 256;
                int n = idx >> 3;
                int kq = (idx & 7) * 4;
                size_t goff = (size_t)(half * 128 + n) * 128 + k0 + kq;
                uint2 uh = *(const uint2*)&W2hi[goff];
                uint2 ul = *(const uint2*)&W2lo[goff];
                int b = n * SBS + kq;
                *(uint32_t*)&sBhi[b]     = uh.x;
                *(uint32_t*)&sBhi[b + 2] = uh.y;
                *(uint32_t*)&sBlo[b]     = ul.x;
                *(uint32_t*)&sBlo[b + 2] = ul.y;
            }
            __syncthreads();

#pragma unroll
            for (int kc = 0; kc < KBLK; kc += 16) {
                int kk = k0 + kc;
                uint32_t ah[2][4], al[2][4];
#pragma unroll
                for (int mf = 0; mf < 2; mf++) {
                    int r = warpRow * 32 + mf * 16 + qrow;
                    int i0 = r * TAS + kk + 2 * qcol;
                    ah[mf][0] = *(const uint32_t*)&sThi[i0];
                    ah[mf][1] = *(const uint32_t*)&sThi[i0 + 8 * TAS];
                    ah[mf][2] = *(const uint32_t*)&sThi[i0 + 8];
                    ah[mf][3] = *(const uint32_t*)&sThi[i0 + 8 * TAS + 8];
                    al[mf][0] = *(const uint32_t*)&sTlo[i0];
                    al[mf][1] = *(const uint32_t*)&sTlo[i0 + 8 * TAS];
                    al[mf][2] = *(const uint32_t*)&sTlo[i0 + 8];
                    al[mf][3] = *(const uint32_t*)&sTlo[i0 + 8 * TAS + 8];
                }
#pragma unroll
                for (int nf = 0; nf < 8; nf++) {
                    int n = warpCol * 64 + nf * 8 + qrow;
                    int i0 = n * SBS + kc + 2 * qcol;
                    uint32_t bh0 = *(const uint32_t*)&sBhi[i0];
                    uint32_t bh1 = *(const uint32_t*)&sBhi[i0 + 8];
                    uint32_t bl0 = *(const uint32_t*)&sBlo[i0];
                    uint32_t bl1 = *(const uint32_t*)&sBlo[i0 + 8];
#pragma unroll
                    for (int mf = 0; mf < 2; mf++) {
                        mma_bf16(c[mf][nf], ah[mf][0], ah[mf][1], ah[mf][2], ah[mf][3], bh0, bh1);
                        mma_bf16(c[mf][nf], ah[mf][0], ah[mf][1], ah[mf][2], ah[mf][3], bl0, bl1);
                        mma_bf16(c[mf][nf], al[mf][0], al[mf][1], al[mf][2], al[mf][3], bh0, bh1);
                    }
                }
            }
        }

        // stage2 epilogue: bias2, packed store (M = 256)
#pragma unroll
        for (int mf = 0; mf < 2; mf++) {
            int rbase = row0 + warpRow * 32 + mf * 16 + qrow;
#pragma unroll
            for (int nf = 0; nf < 8; nf++) {
                int colp = half * 128 + warpCol * 64 + nf * 8 + 2 * qcol;
                float b0v = bias2[colp], b1v = bias2[colp + 1];
                float f0 = c[mf][nf][0] + b0v;
                float f1 = c[mf][nf][1] + b1v;
                float f2 = c[mf][nf][2] + b0v;
                float f3 = c[mf][nf][3] + b1v;
                if (rbase < Nrows)
                    *(uint2*)&C2[(size_t)rbase * 256 + colp] =
                        make_uint2(pack_split(f0), pack_split(f1));
                if (rbase + 8 < Nrows)
                    *(uint2*)&C2[(size_t)(rbase + 8) * 256 + colp] =
                        make_uint2(pack_split(f2), pack_split(f3));
            }
        }
    }
}

// ---------------- hull kernel (unchanged) ----------
#define HULL_SMEM_BYTES ((2 * 128 * HSBS + 2 * HTILE * HSAS) * 2 + (HTILE * 16 + 128) * 4)

__global__ __launch_bounds__(256, 2) void hull_kernel(
    const float* __restrict__ fea,
    const int* __restrict__ jidx, const int* __restrict__ pos,
    const float* __restrict__ w0, const float* __restrict__ b0,
    const float* __restrict__ w1, const float* __restrict__ b1,
    const float* __restrict__ vhull, float* __restrict__ ehull, int EHn)
{
    extern __shared__ char smraw[];
    __nv_bfloat16* s_w1hi  = (__nv_bfloat16*)smraw;
    __nv_bfloat16* s_w1lo  = s_w1hi + 128 * HSBS;
    __nv_bfloat16* s_hidhi = s_w1lo + 128 * HSBS;
    __nv_bfloat16* s_hidlo = s_hidhi + HTILE * HSAS;
    float* s_fea = (float*)(s_hidlo + HTILE * HSAS);
    float* s_b1  = s_fea + HTILE * 16;

    int tid = threadIdx.x;
    int wid = tid >> 5;
    int lane = tid & 31;
    int warpRow = wid & 1;
    int warpCol = wid >> 1;
    int qrow = lane >> 2;
    int qcol = lane & 3;
    int col = tid & 127;
    int wg  = tid >> 7;
    int g  = lane >> 3;
    int lr = lane & 7;

    for (int t = tid; t < 16384; t += 256) {
        int k = t >> 7, n = t & 127;
        float v = w1[t];
        __nv_bfloat16 h = __float2bfloat16(v);
        __nv_bfloat16 l = __float2bfloat16(v - __bfloat162float(h));
        s_w1hi[n * HSBS + k] = h;
        s_w1lo[n * HSBS + k] = l;
    }
    if (tid < 128) s_b1[tid] = b1[tid];
    float rw0[16];
#pragma unroll
    for (int k = 0; k < 16; k++) rw0[k] = w0[k * 128 + col];
    float rb0 = b0[col];

    uint32_t bHhi = smem_u32(s_hidhi), bHlo = smem_u32(s_hidlo);
    uint32_t bWhi = smem_u32(s_w1hi),  bWlo = smem_u32(s_w1lo);
    uint32_t aRowPart = (uint32_t)((warpRow * 16 + (g & 1) * 8 + lr) * HSAS * 2
                                   + (g >> 1) * 16);
    uint32_t bRowPart[2];
#pragma unroll
    for (int p = 0; p < 2; p++)
        bRowPart[p] = (uint32_t)(((warpCol * 32 + (2 * p + (g >> 1)) * 8 + lr) * HSBS
                                  + (g & 1) * 8) * 2);
    __syncthreads();

    for (int base = blockIdx.x * HTILE; base < EHn; base += gridDim.x * HTILE) {
        int ec = min(HTILE, EHn - base);

        for (int t = tid; t < ec * 16; t += 256)
            s_fea[t] = fea[(size_t)base * 16 + t];
        __syncthreads();

        int e0 = wg * 16, e1 = min(ec, e0 + 16);
        for (int e = e0; e < e1; e++) {
            float acc = rb0;
#pragma unroll
            for (int k = 0; k < 16; k++)
                acc += s_fea[e * 16 + k] * rw0[k];
            float hv = silu_f(acc);
            __nv_bfloat16 h = __float2bfloat16(hv);
            __nv_bfloat16 l = __float2bfloat16(hv - __bfloat162float(h));
            s_hidhi[e * HSAS + col] = h;
            s_hidlo[e * HSAS + col] = l;
        }
        __syncthreads();

        float c[4][4];
#pragma unroll
        for (int nf = 0; nf < 4; nf++)
#pragma unroll
            for (int q = 0; q < 4; q++) c[nf][q] = 0.0f;

#pragma unroll
        for (int kc = 0; kc < 128; kc += 16) {
            uint32_t kOff = kc * 2;
            uint32_t ah0, ah1, ah2, ah3, al0, al1, al2, al3;
            ldmx4(ah0, ah1, ah2, ah3, bHhi + aRowPart + kOff);
            ldmx4(al0, al1, al2, al3, bHlo + aRowPart + kOff);
#pragma unroll
            for (int p = 0; p < 2; p++) {
                uint32_t bh0, bh1, bh2, bh3, bl0, bl1, bl2, bl3;
                ldmx4(bh0, bh1, bh2, bh3, bWhi + bRowPart[p] + kOff);
                ldmx4(bl0, bl1, bl2, bl3, bWlo + bRowPart[p] + kOff);
                mma_bf16(c[2*p],   ah0, ah1, ah2, ah3, bh0, bh1);
                mma_bf16(c[2*p],   ah0, ah1, ah2, ah3, bl0, bl1);
                mma_bf16(c[2*p],   al0, al1, al2, al3, bh0, bh1);
                mma_bf16(c[2*p+1], ah0, ah1, ah2, ah3, bh2, bh3);
                mma_bf16(c[2*p+1], ah0, ah1, ah2, ah3, bl2, bl3);
                mma_bf16(c[2*p+1], al0, al1, al2, al3, bh2, bh3);
            }
        }

        int eA = warpRow * 16 + qrow;
        int eB = eA + 8;
        int jA = 0, sA = 0, jB = 0, sB = 0;
        bool vA = eA < ec, vB = eB < ec;
        if (vA) { jA = jidx[base + eA]; sA = pos[base + eA]; }
        if (vB) { jB = jidx[base + eB]; sB = pos[base + eB]; }
#pragma unroll
        for (int nf = 0; nf < 4; nf++) {
            int cp = warpCol * 32 + nf * 8 + 2 * qcol;
            float bb0 = s_b1[cp], bb1 = s_b1[cp + 1];
            if (vA) {
                float2 vh = *(const float2*)&vhull[(size_t)jA * 128 + cp];
                *(float2*)&ehull[(size_t)sA * 128 + cp] =
                    make_float2((c[nf][0] + bb0) * vh.x, (c[nf][1] + bb1) * vh.y);
            }
            if (vB) {
                float2 vh = *(const float2*)&vhull[(size_t)jB * 128 + cp];
                *(float2*)&ehull[(size_t)sB * 128 + cp] =
                    make_float2((c[nf][2] + bb0) * vh.x, (c[nf][3] + bb1) * vh.y);
            }
        }
        __syncthreads();
    }
}

// ---------------- launch ----------------
static void launch_gemm(const uint32_t* A0, int lda0, int ksplit,
                        const uint32_t* A1, int lda1,
                        const __nv_bfloat16* whiT, const __nv_bfloat16* wloT, int ldw,
                        const float* bias, void* C, int outPacked,
                        const float* wout, float* outv,
                        int N, int K, int M, int act)
{
    dim3 grid((N + 127) / 128, M / 128);
    gemm_mma<<<grid, 256>>>(A0, lda0, ksplit, A1, lda1, whiT, wloT, ldw,
                            bias, C, outPacked, wout, outv, N, K, M, act);
}

extern "C" void kernel_launch(void* const* d_in, const int* in_sizes, int n_in,
                              void* d_out, int out_size)
{
    const float* e2    = (const float*)d_in[0];
    const int*   iedge = (const int*)  d_in[1];
    const float* fea   = (const float*)d_in[2];
    const int*   eih   = (const int*)  d_in[3];
    const float* w_hull= (const float*)d_in[4];
    const float* w0    = (const float*)d_in[5];
    const float* b0    = (const float*)d_in[6];
    const float* w1    = (const float*)d_in[7];
    const float* b1    = (const float*)d_in[8];
    const float* w1h   = (const float*)d_in[9];
    const float* b1h   = (const float*)d_in[10];
    const float* w2h   = (const float*)d_in[11];
    const float* b2h   = (const float*)d_in[12];
    const float* wcat  = (const float*)d_in[13];
    const float* bcat  = (const float*)d_in[14];
    const float* wup   = (const float*)d_in[15];
    const float* bup   = (const float*)d_in[16];
    const float* wl0   = (const float*)d_in[17];
    const float* bl0   = (const float*)d_in[18];
    const float* wl1   = (const float*)d_in[19];
    const float* bl1   = (const float*)d_in[20];
    const float* wout  = (const float*)d_in[21];
    float* out = (float*)d_out;

    int N  = out_size;
    int E  = in_sizes[1];
    int EH = in_sizes[2] / 16;
    const int* jh = eih;
    const int* ih = eih + EH;

    float *pvh, *peh;
    uint32_t *pvp, *pohp, *pa256p, *pb256p;
    __nv_bfloat16 *pwhi, *pwlo;
    int *pcnt, *poff, *prun, *ppart, *peord;
    int *pcnt2, *poff2, *prun2, *ppart2, *ppos;
    cudaGetSymbolAddress((void**)&pvh,    g_vhull);
    cudaGetSymbolAddress((void**)&peh,    g_ehull);
    cudaGetSymbolAddress((void**)&pvp,    g_vp);
    cudaGetSymbolAddress((void**)&pohp,   g_ohp);
    cudaGetSymbolAddress((void**)&pa256p, g_a256p);
    cudaGetSymbolAddress((void**)&pb256p, g_b256p);
    cudaGetSymbolAddress((void**)&pwhi,   g_whi);
    cudaGetSymbolAddress((void**)&pwlo,   g_wlo);
    cudaGetSymbolAddress((void**)&pcnt,   g_counts);
    cudaGetSymbolAddress((void**)&poff,   g_offsets);
    cudaGetSymbolAddress((void**)&prun,   g_running);
    cudaGetSymbolAddress((void**)&ppart,  g_partial);
    cudaGetSymbolAddress((void**)&peord,  g_eorder);
    cudaGetSymbolAddress((void**)&pcnt2,  g_counts2);
    cudaGetSymbolAddress((void**)&poff2,  g_offsets2);
    cudaGetSymbolAddress((void**)&prun2,  g_running2);
    cudaGetSymbolAddress((void**)&ppart2, g_partial2);
    cudaGetSymbolAddress((void**)&ppos,   g_pos);

    cudaFuncSetAttribute(hull_kernel, cudaFuncAttributeMaxDynamicSharedMemorySize,
                         HULL_SMEM_BYTES);
    cudaFuncSetAttribute(hull_kernel, cudaFuncAttributePreferredSharedMemoryCarveout,
                         100);
    cudaFuncSetAttribute(gemm2_mma, cudaFuncAttributeMaxDynamicSharedMemorySize,
                         GEMM2_SMEM_BYTES);

    // 0. pre-split ALL weights in one launch
    {
        WSpec s0 = { w_hull, OFF_WHULL, 128, 128, 0 };
        WSpec s1 = { w1h,    OFF_W1H,   128, 128, 16384 };
        WSpec s2 = { w2h,    OFF_W2H,   128, 256, 32768 };
        WSpec s3 = { wcat,   OFF_WCAT,  384, 128, 65536 };
        WSpec s4 = { wup,    OFF_WUP,   128, 256, 114688 };
        WSpec s5 = { wl0,    OFF_WL0,   256, 256, 147456 };
        WSpec s6 = { wl1,    OFF_WL1,   256, 256, 212992 };
        pack_all_weights_kernel<<<(WPLANE_TOTAL + 255) / 256, 256>>>(
            s0, s1, s2, s3, s4, s5, s6, WPLANE_TOTAL);
    }

    // 1. zero counts (both) + out
    zero_kernel<<<512, 256>>>(pcnt, pcnt2, out, N);

    // 2. fused CSR build for BOTH graphs
    int nb = (N + 1023) / 1024;
    hist_both_kernel<<<(E + EH + 255) / 256, 256>>>(iedge, E, ih, EH, pcnt, pcnt2);
    scanA_both_kernel<<<2 * nb, 1024>>>(pcnt, poff, ppart, pcnt2, poff2, ppart2, N, nb);
    scanB_both_kernel<<<1, 32>>>(ppart, ppart2, nb);
    scanC_both_kernel<<<(2 * N + 255) / 256, 256>>>(poff, ppart, prun,
                                                    poff2, ppart2, prun2, N);
    fill_both_kernel<<<(E + EH + 255) / 256, 256>>>(iedge, E, prun, peord,
                                                    ih, EH, prun2, ppos);
    csr_sum_kernel<<<(N * 32 + 255) / 256, 256>>>(
        (const float4*)e2, peord, poff, pcnt, pvp, N);

    // 3. v_hull = v @ w_hull
    launch_gemm(pvp, 128, 128, pvp, 128, pwhi + OFF_WHULL, pwlo + OFF_WHULL, 128,
                nullptr, pvh, 0, nullptr, nullptr, N, 128, 128, 0);

    // 4. hull message passing + reduce -> packed ohp
    hull_kernel<<<296, 256, HULL_SMEM_BYTES>>>(
        fea, jh, ppos, w0, b0, w1, b1, pvh, peh, EH);
    hull_reduce_kernel<<<(N * 32 + 255) / 256, 256>>>(
        (const float4*)peh, poff2, pcnt2, pohp, N);

    // 5+6 fused: a256 = silu(ohp @ w1_hull + b1h) @ w2_hull + b2h
    {
        int blocks = (N + 127) / 128;
        gemm2_mma<<<blocks, 256, GEMM2_SMEM_BYTES>>>(
            pohp, 128, 128, pohp, 128,
            pwhi + OFF_W1H, pwlo + OFF_W1H, 128, b1h,
            pwhi + OFF_W2H, pwlo + OFF_W2H, b2h,
            pa256p, N, 128);
    }

    // 7+8 fused: b256 = silu([v|a256] @ w_cat + bcat) @ w_up + bup
    {
        int blocks = (N + 127) / 128;
        gemm2_mma<<<blocks, 256, GEMM2_SMEM_BYTES>>>(
            pvp, 128, 128, pa256p, 256,
            pwhi + OFF_WCAT, pwlo + OFF_WCAT, 384, bcat,
            pwhi + OFF_WUP, pwlo + OFF_WUP, bup,
            pb256p, N, 384);
    }

    // 9. a256p = silu(b256 @ w_l0 + b_l0)
    launch_gemm(pb256p, 256, 256, pb256p, 256, pwhi + OFF_WL0, pwlo + OFF_WL0, 256,
                bl0, pa256p, 1, nullptr, nullptr, N, 256, 256, 1);
    // 10+11 fused: out += silu(a256 @ w_l1 + b_l1) . w_out
    launch_gemm(pa256p, 256, 256, pa256p, 256, pwhi + OFF_WL1, pwlo + OFF_WL1, 256,
                bl1, nullptr, 0, wout, out, N, 256, 256, 1);
}